// round 1
// baseline (speedup 1.0000x reference)
#include <cuda_runtime.h>
#include <cstdint>

// ---------------- problem constants ----------------
#define HD   256      // hidden / embedding dim
#define G3   768      // 3*H gate dim
#define VOCAB 30000
#define NW   2048     // word-level sequences (B*R*S)
#define TW   32       // word-level timesteps (W)
#define NS   128      // sentence-level sequences (B*R)
#define TS   16       // sentence-level timesteps (S)
#define NR   8        // review-level sequences (B)
#define TR   16       // review-level timesteps (R)

// ---------------- scratch (static device globals; no runtime alloc) ----------------
__device__ float g_PV [(size_t)2*VOCAB*G3];        // projected vocab per dir (~184MB)
__device__ float g_GXw[(size_t)2*NW*TW*G3];        // word-level gx (~403MB)
__device__ float g_GXs[(size_t)2*NS*TS*G3];        // sentence-level gx
__device__ float g_GXr[(size_t)2*NR*TR*G3];        // review-level gx
__device__ float g_Hw [2][(size_t)2*NW*HD];        // ping-pong hidden, word
__device__ float g_Hs [2][(size_t)2*NS*HD];        // sentence
__device__ float g_Hr [2][(size_t)2*NR*HD];        // review
__device__ float g_Xs [(size_t)NW*HD];             // sentence vectors (h_f+h_b)
__device__ float g_Xr [(size_t)NS*HD];             // review vectors
__device__ float g_Xb [(size_t)NR*HD];             // business vectors

// ---------------- helpers ----------------
__device__ __forceinline__ float sigm(float x) { return 1.f / (1.f + expf(-x)); }

__global__ void kzero(float* p, size_t n) {
    size_t i = (size_t)blockIdx.x * blockDim.x + threadIdx.x;
    size_t stride = (size_t)gridDim.x * blockDim.x;
    for (; i < n; i += stride) p[i] = 0.f;
}

// ---------------- GEMM: C[d][M,768] = A[M,256] @ W[d][768,256]^T + bias[d] ----------------
// grid: (ceil(M/128), 768/64, 2), block 256
__global__ __launch_bounds__(256)
void gemm_proj(const float* __restrict__ A, int M,
               const float* __restrict__ W, const float* __restrict__ bias,
               float* __restrict__ C)
{
    int d = blockIdx.z;
    const float* Wd = W    + (size_t)d * G3 * HD;
    const float* bd = bias + (size_t)d * G3;
    float*       Cd = C    + (size_t)d * M * G3;

    int m0 = blockIdx.x * 128;
    int n0 = blockIdx.y * 64;

    __shared__ float As[32][129];
    __shared__ float Bs[32][65];

    int tid = threadIdx.x;
    int ty = tid >> 4, tx = tid & 15;   // 16x16

    float acc[8][4];
#pragma unroll
    for (int i = 0; i < 8; ++i)
#pragma unroll
        for (int j = 0; j < 4; ++j) acc[i][j] = 0.f;

    for (int k0 = 0; k0 < 256; k0 += 32) {
#pragma unroll
        for (int it = 0; it < 4; ++it) {      // A tile: 128 rows x 32 k = 1024 float4
            int slot = tid + it * 256;
            int m = slot >> 3, kq = slot & 7;
            float4 v = make_float4(0.f, 0.f, 0.f, 0.f);
            if (m0 + m < M)
                v = *(const float4*)(A + (size_t)(m0 + m) * 256 + k0 + kq * 4);
            As[kq*4+0][m] = v.x; As[kq*4+1][m] = v.y;
            As[kq*4+2][m] = v.z; As[kq*4+3][m] = v.w;
        }
#pragma unroll
        for (int it = 0; it < 2; ++it) {      // W tile: 64 rows x 32 k
            int slot = tid + it * 256;
            int n = slot >> 3, kq = slot & 7;
            float4 v = *(const float4*)(Wd + (size_t)(n0 + n) * 256 + k0 + kq * 4);
            Bs[kq*4+0][n] = v.x; Bs[kq*4+1][n] = v.y;
            Bs[kq*4+2][n] = v.z; Bs[kq*4+3][n] = v.w;
        }
        __syncthreads();
#pragma unroll
        for (int k = 0; k < 32; ++k) {
            float a[8], b[4];
#pragma unroll
            for (int i = 0; i < 8; ++i) a[i] = As[k][ty*8 + i];
#pragma unroll
            for (int j = 0; j < 4; ++j) b[j] = Bs[k][tx*4 + j];
#pragma unroll
            for (int i = 0; i < 8; ++i)
#pragma unroll
                for (int j = 0; j < 4; ++j) acc[i][j] += a[i] * b[j];
        }
        __syncthreads();
    }

    float4 bb = *(const float4*)(bd + n0 + tx*4);
#pragma unroll
    for (int i = 0; i < 8; ++i) {
        int m = m0 + ty*8 + i;
        if (m < M) {
            float4 o;
            o.x = acc[i][0] + bb.x; o.y = acc[i][1] + bb.y;
            o.z = acc[i][2] + bb.z; o.w = acc[i][3] + bb.w;
            *(float4*)(Cd + (size_t)m * G3 + n0 + tx*4) = o;
        }
    }
}

// ---------------- gather projected vocab rows into word-level GX ----------------
// tokens: possibly int32 or int64 (low-word layout detected at runtime)
__global__ void gather_gx(const int* __restrict__ raw)
{
    size_t id = (size_t)blockIdx.x * blockDim.x + threadIdx.x;   // over 2*65536*192
    const size_t total = (size_t)2 * NW * TW * 192;
    if (id >= total) return;
    int q = (int)(id % 192);
    size_t rp = id / 192;
    int p = (int)(rp % ((size_t)NW * TW));
    int d = (int)(rp / ((size_t)NW * TW));
    // int64 detection: non-negative int64 tokens have zero high words
    bool is64 = (raw[1] == 0) & (raw[3] == 0) & (raw[5] == 0) & (raw[7] == 0);
    int tok = is64 ? raw[2 * (size_t)p] : raw[p];
    float4 v = *(const float4*)(g_PV + ((size_t)d * VOCAB + tok) * G3 + q * 4);
    *(float4*)(g_GXw + ((size_t)d * NW * TW + p) * G3 + q * 4) = v;
}

// ---------------- fused GRU step ----------------
// One launch per timestep. Each CTA: 64 rows x 64 h-columns; computes the three
// gate column blocks (j, 256+j, 512+j) of Gh = H @ Whh^T, then the gate math.
// grid: (ceil(N/64), 4, 2), block 256
__global__ __launch_bounds__(256)
void gru_step(const float* __restrict__ Hin, float* __restrict__ Hout,
              const float* __restrict__ Whh,   // [2][768][256]
              const float* __restrict__ bhh,   // [2][768]
              const float* __restrict__ GX,    // [2][N*T][768], row = n*T + t
              int N, int T, int t)
{
    int d  = blockIdx.z;
    int n0 = blockIdx.x * 64;
    int j0 = blockIdx.y * 64;
    int teff = (d == 0) ? t : (T - 1 - t);

    const float* Wd = Whh + (size_t)d * G3 * HD;

    __shared__ float Hs[32][65];
    __shared__ float Ws[3][32][65];

    int tid = threadIdx.x;
    int ty = tid >> 4, tx = tid & 15;   // 16x16; thread: 4 rows x 4 cols x 3 gates

    float accR[4][4], accZ[4][4], accN[4][4];
#pragma unroll
    for (int i = 0; i < 4; ++i)
#pragma unroll
        for (int j = 0; j < 4; ++j) { accR[i][j] = 0.f; accZ[i][j] = 0.f; accN[i][j] = 0.f; }

    for (int k0 = 0; k0 < 256; k0 += 32) {
#pragma unroll
        for (int it = 0; it < 2; ++it) {      // H tile 64x32
            int slot = tid + it * 256;
            int m = slot >> 3, kq = slot & 7;
            float4 v = make_float4(0.f, 0.f, 0.f, 0.f);
            if (n0 + m < N)
                v = *(const float4*)(Hin + (size_t)(d * N + n0 + m) * HD + k0 + kq * 4);
            Hs[kq*4+0][m] = v.x; Hs[kq*4+1][m] = v.y;
            Hs[kq*4+2][m] = v.z; Hs[kq*4+3][m] = v.w;
        }
#pragma unroll
        for (int g = 0; g < 3; ++g) {
#pragma unroll
            for (int it = 0; it < 2; ++it) {  // W gate tile 64x32
                int slot = tid + it * 256;
                int m = slot >> 3, kq = slot & 7;
                int gg = g * 256 + j0 + m;
                float4 v = *(const float4*)(Wd + (size_t)gg * HD + k0 + kq * 4);
                Ws[g][kq*4+0][m] = v.x; Ws[g][kq*4+1][m] = v.y;
                Ws[g][kq*4+2][m] = v.z; Ws[g][kq*4+3][m] = v.w;
            }
        }
        __syncthreads();
#pragma unroll
        for (int k = 0; k < 32; ++k) {
            float a[4];
#pragma unroll
            for (int i = 0; i < 4; ++i) a[i] = Hs[k][ty*4 + i];
#pragma unroll
            for (int j = 0; j < 4; ++j) {
                float wr = Ws[0][k][tx*4 + j];
                float wz = Ws[1][k][tx*4 + j];
                float wn = Ws[2][k][tx*4 + j];
#pragma unroll
                for (int i = 0; i < 4; ++i) {
                    accR[i][j] += a[i] * wr;
                    accZ[i][j] += a[i] * wz;
                    accN[i][j] += a[i] * wn;
                }
            }
        }
        __syncthreads();
    }

    int c = j0 + tx * 4;
    float4 br4 = *(const float4*)(bhh + (size_t)d * G3 + c);
    float4 bz4 = *(const float4*)(bhh + (size_t)d * G3 + 256 + c);
    float4 bn4 = *(const float4*)(bhh + (size_t)d * G3 + 512 + c);
    const float* brp = &br4.x; const float* bzp = &bz4.x; const float* bnp = &bn4.x;

#pragma unroll
    for (int i = 0; i < 4; ++i) {
        int n = n0 + ty * 4 + i;
        if (n >= N) continue;
        const float* gxrow = GX + ((size_t)d * N * T + (size_t)n * T + teff) * G3;
        float4 gr = *(const float4*)(gxrow + c);
        float4 gz = *(const float4*)(gxrow + 256 + c);
        float4 gn = *(const float4*)(gxrow + 512 + c);
        float4 h4 = *(const float4*)(Hin + (size_t)(d * N + n) * HD + c);
        const float* grp = &gr.x; const float* gzp = &gz.x;
        const float* gnp = &gn.x; const float* hp  = &h4.x;
        float4 o; float* op = &o.x;
#pragma unroll
        for (int j = 0; j < 4; ++j) {
            float r  = sigm(grp[j] + accR[i][j] + brp[j]);
            float z  = sigm(gzp[j] + accZ[i][j] + bzp[j]);
            float nn = tanhf(gnp[j] + r * (accN[i][j] + bnp[j]));
            op[j] = (1.f - z) * nn + z * hp[j];
        }
        *(float4*)(Hout + (size_t)(d * N + n) * HD + c) = o;
    }
}

// ---------------- sum forward+backward final hidden ----------------
__global__ void sum_dirs(const float* __restrict__ Hf, float* __restrict__ out, int N)
{
    int i = blockIdx.x * 256 + threadIdx.x;
    if (i < N * HD) out[i] = Hf[i] + Hf[(size_t)N * HD + i];
}

// ---------------- FC head: Linear(256->128) -> SELU -> Linear(128->1) ----------------
__global__ void fc_head(const float* __restrict__ X,
                        const float* __restrict__ W1, const float* __restrict__ b1,
                        const float* __restrict__ W2, const float* __restrict__ b2,
                        float* __restrict__ out)
{
    int row = blockIdx.x;
    int h = threadIdx.x;  // 128 threads
    const float* x = X + (size_t)row * HD;
    const float* w = W1 + (size_t)h * HD;
    float s = 0.f;
#pragma unroll 8
    for (int k = 0; k < HD; k += 4) {
        float4 xv = *(const float4*)(x + k);
        float4 wv = *(const float4*)(w + k);
        s += xv.x * wv.x + xv.y * wv.y + xv.z * wv.z + xv.w * wv.w;
    }
    s += b1[h];
    const float SC = 1.0507009873554805f, AL = 1.6732632423543772f;
    float selu = SC * (s > 0.f ? s : AL * expm1f(s));
    float v = selu * W2[h];
    __shared__ float red[128];
    red[h] = v; __syncthreads();
    for (int st = 64; st > 0; st >>= 1) {
        if (h < st) red[h] += red[h + st];
        __syncthreads();
    }
    if (h == 0) out[row] = red[0] + b2[0];
}

// ---------------- launch ----------------
extern "C" void kernel_launch(void* const* d_in, const int* in_sizes, int n_in,
                              void* d_out, int out_size)
{
    const int*   tok   = (const int*)  d_in[0];
    const float* emb   = (const float*)d_in[1];
    const float* wWih  = (const float*)d_in[2];
    const float* wWhh  = (const float*)d_in[3];
    const float* wbih  = (const float*)d_in[4];
    const float* wbhh  = (const float*)d_in[5];
    const float* sWih  = (const float*)d_in[6];
    const float* sWhh  = (const float*)d_in[7];
    const float* sbih  = (const float*)d_in[8];
    const float* sbhh  = (const float*)d_in[9];
    const float* rWih  = (const float*)d_in[10];
    const float* rWhh  = (const float*)d_in[11];
    const float* rbih  = (const float*)d_in[12];
    const float* rbhh  = (const float*)d_in[13];
    const float* rfcW1 = (const float*)d_in[14];
    const float* rfcb1 = (const float*)d_in[15];
    const float* rfcW2 = (const float*)d_in[16];
    const float* rfcb2 = (const float*)d_in[17];
    const float* pfcW1 = (const float*)d_in[18];
    const float* pfcb1 = (const float*)d_in[19];
    const float* pfcW2 = (const float*)d_in[20];
    const float* pfcb2 = (const float*)d_in[21];
    float* out = (float*)d_out;

    float *pv, *gxw, *gxs, *gxr, *hwB, *hsB, *hrB, *xs, *xr, *xb;
    cudaGetSymbolAddress((void**)&pv,  g_PV);
    cudaGetSymbolAddress((void**)&gxw, g_GXw);
    cudaGetSymbolAddress((void**)&gxs, g_GXs);
    cudaGetSymbolAddress((void**)&gxr, g_GXr);
    cudaGetSymbolAddress((void**)&hwB, g_Hw);
    cudaGetSymbolAddress((void**)&hsB, g_Hs);
    cudaGetSymbolAddress((void**)&hrB, g_Hr);
    cudaGetSymbolAddress((void**)&xs,  g_Xs);
    cudaGetSymbolAddress((void**)&xr,  g_Xr);
    cudaGetSymbolAddress((void**)&xb,  g_Xb);

    float* hw[2] = { hwB, hwB + (size_t)2 * NW * HD };
    float* hs[2] = { hsB, hsB + (size_t)2 * NS * HD };
    float* hr[2] = { hrB, hrB + (size_t)2 * NR * HD };

    // zero initial hidden states
    kzero<<<2048, 256>>>(hw[0], (size_t)2 * NW * HD);
    kzero<<<256,  256>>>(hs[0], (size_t)2 * NS * HD);
    kzero<<<16,   256>>>(hr[0], (size_t)2 * NR * HD);

    // project full vocabulary once per direction: PV = emb @ Wih^T + bih
    gemm_proj<<<dim3((VOCAB + 127) / 128, G3 / 64, 2), 256>>>(emb, VOCAB, wWih, wbih, pv);

    // gather token projections -> word-level GX
    {
        size_t total = (size_t)2 * NW * TW * 192;
        gather_gx<<<(unsigned)((total + 255) / 256), 256>>>(tok);
    }

    // word-level scan (T=32)
    for (int t = 0; t < TW; ++t)
        gru_step<<<dim3(NW / 64, 4, 2), 256>>>(hw[t & 1], hw[(t + 1) & 1],
                                               wWhh, wbhh, gxw, NW, TW, t);
    sum_dirs<<<(NW * HD) / 256, 256>>>(hw[TW & 1], xs, NW);

    // sentence-level: project + scan (T=16)
    gemm_proj<<<dim3((NW + 127) / 128, G3 / 64, 2), 256>>>(xs, NW, sWih, sbih, gxs);
    for (int t = 0; t < TS; ++t)
        gru_step<<<dim3((NS + 63) / 64, 4, 2), 256>>>(hs[t & 1], hs[(t + 1) & 1],
                                                      sWhh, sbhh, gxs, NS, TS, t);
    sum_dirs<<<(NS * HD) / 256, 256>>>(hs[TS & 1], xr, NS);

    // review-star head on review vectors -> out[8..135]
    fc_head<<<NS, 128>>>(xr, rfcW1, rfcb1, rfcW2, rfcb2, out + NR);

    // review-level (business) biGRU: project + scan (T=16)
    gemm_proj<<<dim3(1, G3 / 64, 2), 256>>>(xr, NS, rWih, rbih, gxr);
    for (int t = 0; t < TR; ++t)
        gru_step<<<dim3(1, 4, 2), 256>>>(hr[t & 1], hr[(t + 1) & 1],
                                         rWhh, rbhh, gxr, NR, TR, t);
    sum_dirs<<<(NR * HD) / 256, 256>>>(hr[TR & 1], xb, NR);

    // business head -> out[0..7]
    fc_head<<<NR, 128>>>(xb, pfcW1, pfcb1, pfcW2, pfcb2, out);

    (void)in_sizes; (void)n_in; (void)out_size;
}

// round 2
// speedup vs baseline: 1.2064x; 1.2064x over previous
#include <cuda_runtime.h>
#include <cstdint>

// ---------------- problem constants ----------------
#define HD   256      // hidden / embedding dim
#define G3   768      // 3*H gate dim
#define VOCAB 30000
#define NW   2048     // word-level sequences (B*R*S)
#define TW   32       // word-level timesteps (W)
#define NS   128      // sentence-level sequences (B*R)
#define TS   16       // sentence-level timesteps (S)
#define NR   8        // review-level sequences (B)
#define TR   16       // review-level timesteps (R)

// ---------------- scratch (static device globals; no runtime alloc) ----------------
__device__ float g_PV [(size_t)2*VOCAB*G3];        // projected vocab per dir (~184MB)
__device__ float g_GXs[(size_t)2*NS*TS*G3];        // sentence-level gx
__device__ float g_GXr[(size_t)2*NR*TR*G3];        // review-level gx
__device__ float g_Hw [2][(size_t)2*NW*HD];        // ping-pong hidden, word
__device__ float g_Hs [2][(size_t)2*NS*HD];        // sentence
__device__ float g_Hr [2][(size_t)2*NR*HD];        // review
__device__ float g_Xs [(size_t)NW*HD];             // sentence vectors (h_f+h_b)
__device__ float g_Xr [(size_t)NS*HD];             // review vectors
__device__ float g_Xb [(size_t)NR*HD];             // business vectors

// ---------------- helpers ----------------
__device__ __forceinline__ float sigm(float x) { return 1.f / (1.f + expf(-x)); }

__device__ __forceinline__ unsigned f2tf(float x) {
    unsigned u;
    asm("cvt.rna.tf32.f32 %0, %1;" : "=r"(u) : "f"(x));
    return u;
}

__device__ __forceinline__ void mma8(float* d,
                                     unsigned a0, unsigned a1, unsigned a2, unsigned a3,
                                     unsigned b0, unsigned b1) {
    asm volatile(
        "mma.sync.aligned.m16n8k8.row.col.f32.tf32.tf32.f32 "
        "{%0,%1,%2,%3},{%4,%5,%6,%7},{%8,%9},{%0,%1,%2,%3};"
        : "+f"(d[0]), "+f"(d[1]), "+f"(d[2]), "+f"(d[3])
        : "r"(a0), "r"(a1), "r"(a2), "r"(a3), "r"(b0), "r"(b1));
}

__global__ void kzero(float* p, size_t n) {
    size_t i = (size_t)blockIdx.x * blockDim.x + threadIdx.x;
    size_t stride = (size_t)gridDim.x * blockDim.x;
    for (; i < n; i += stride) p[i] = 0.f;
}

// ---------------- TF32 GEMM: C[d][M,768] = A[M,256] @ W[d][768,256]^T + bias[d] ----------------
// grid: (ceil(M/128), 768/64, 2), block 256 (8 warps; warp tile 32x32)
__global__ __launch_bounds__(256)
void gemm_proj_mma(const float* __restrict__ A, int M,
                   const float* __restrict__ W, const float* __restrict__ bias,
                   float* __restrict__ C)
{
    int d = blockIdx.z;
    const float* Wd = W    + (size_t)d * G3 * HD;
    const float* bd = bias + (size_t)d * G3;
    float*       Cd = C    + (size_t)d * M * G3;

    int m0 = blockIdx.x * 128;
    int n0 = blockIdx.y * 64;

    __shared__ unsigned As[128][33];
    __shared__ unsigned Ws[64][33];

    int tid = threadIdx.x, lane = tid & 31, wid = tid >> 5;
    int wm = wid & 3, wn = wid >> 2;          // warp grid 4(m) x 2(n)
    int g = lane >> 2, c = lane & 3;

    float acc[2][4][4];
#pragma unroll
    for (int i = 0; i < 2; ++i)
#pragma unroll
        for (int j = 0; j < 4; ++j)
#pragma unroll
            for (int k = 0; k < 4; ++k) acc[i][j][k] = 0.f;

    for (int k0 = 0; k0 < 256; k0 += 32) {
#pragma unroll
        for (int it = 0; it < 4; ++it) {         // A tile 128x32
            int slot = tid + it * 256;
            int r = slot >> 3, q = slot & 7;
            float4 v = make_float4(0.f, 0.f, 0.f, 0.f);
            if (m0 + r < M)
                v = *(const float4*)(A + (size_t)(m0 + r) * HD + k0 + q * 4);
            As[r][q*4+0] = f2tf(v.x); As[r][q*4+1] = f2tf(v.y);
            As[r][q*4+2] = f2tf(v.z); As[r][q*4+3] = f2tf(v.w);
        }
#pragma unroll
        for (int it = 0; it < 2; ++it) {         // W tile 64x32 (row = gate col n)
            int slot = tid + it * 256;
            int r = slot >> 3, q = slot & 7;
            float4 v = *(const float4*)(Wd + (size_t)(n0 + r) * HD + k0 + q * 4);
            Ws[r][q*4+0] = f2tf(v.x); Ws[r][q*4+1] = f2tf(v.y);
            Ws[r][q*4+2] = f2tf(v.z); Ws[r][q*4+3] = f2tf(v.w);
        }
        __syncthreads();
#pragma unroll
        for (int ks = 0; ks < 4; ++ks) {
            int kb = ks * 8;
            unsigned a[2][4];
#pragma unroll
            for (int mt = 0; mt < 2; ++mt) {
                int br = wm * 32 + mt * 16;
                a[mt][0] = As[br + g    ][kb + c    ];
                a[mt][1] = As[br + g + 8][kb + c    ];
                a[mt][2] = As[br + g    ][kb + c + 4];
                a[mt][3] = As[br + g + 8][kb + c + 4];
            }
#pragma unroll
            for (int nt = 0; nt < 4; ++nt) {
                int bn = wn * 32 + nt * 8 + g;
                unsigned b0 = Ws[bn][kb + c];
                unsigned b1 = Ws[bn][kb + c + 4];
#pragma unroll
                for (int mt = 0; mt < 2; ++mt)
                    mma8(acc[mt][nt], a[mt][0], a[mt][1], a[mt][2], a[mt][3], b0, b1);
            }
        }
        __syncthreads();
    }

#pragma unroll
    for (int nt = 0; nt < 4; ++nt) {
        int col = n0 + wn * 32 + nt * 8 + 2 * c;
        float2 bb = *(const float2*)(bd + col);
#pragma unroll
        for (int mt = 0; mt < 2; ++mt) {
            int row0 = m0 + wm * 32 + mt * 16 + g;
            if (row0 < M) {
                float2 o = make_float2(acc[mt][nt][0] + bb.x, acc[mt][nt][1] + bb.y);
                *(float2*)(Cd + (size_t)row0 * G3 + col) = o;
            }
            int row1 = row0 + 8;
            if (row1 < M) {
                float2 o = make_float2(acc[mt][nt][2] + bb.x, acc[mt][nt][3] + bb.y);
                *(float2*)(Cd + (size_t)row1 * G3 + col) = o;
            }
        }
    }
}

// ---------------- fused TF32-MMA GRU step ----------------
// CTA: 64 rows x 64 h-cols (3 gate blocks j, 256+j, 512+j). Word level reads gx
// rows directly from the projected vocab table via tokens (tok != nullptr).
// grid: (ceil(N/64), 4, 2), block 256 (8 warps; warp tile 16 rows x 32 cols x 3 gates)
__global__ __launch_bounds__(256)
void gru_step_mma(const float* __restrict__ Hin, float* __restrict__ Hout,
                  const float* __restrict__ Whh,   // [2][768][256]
                  const float* __restrict__ bhh,   // [2][768]
                  const float* __restrict__ GX,    // [2][N*T][768] or nullptr
                  const float* __restrict__ PV,    // [2][VOCAB][768] or nullptr
                  const int*   __restrict__ tok,   // word-level tokens or nullptr
                  int N, int T, int t)
{
    int d  = blockIdx.z;
    int n0 = blockIdx.x * 64;
    int j0 = blockIdx.y * 64;
    int teff = d ? (T - 1 - t) : t;

    const float* Wd = Whh + (size_t)d * G3 * HD;

    __shared__ unsigned Hs[64][33];
    __shared__ unsigned Ws[3][64][33];

    int tid = threadIdx.x, lane = tid & 31, wid = tid >> 5;
    int wm = wid & 3, wn = wid >> 2;          // warp grid 4(m) x 2(n)
    int g = lane >> 2, c = lane & 3;

    float acc[3][4][4];
#pragma unroll
    for (int i = 0; i < 3; ++i)
#pragma unroll
        for (int j = 0; j < 4; ++j)
#pragma unroll
            for (int k = 0; k < 4; ++k) acc[i][j][k] = 0.f;

    for (int k0 = 0; k0 < 256; k0 += 32) {
#pragma unroll
        for (int it = 0; it < 2; ++it) {         // H tile 64x32
            int slot = tid + it * 256;
            int r = slot >> 3, q = slot & 7;
            float4 v = make_float4(0.f, 0.f, 0.f, 0.f);
            if (n0 + r < N)
                v = *(const float4*)(Hin + (size_t)(d * N + n0 + r) * HD + k0 + q * 4);
            Hs[r][q*4+0] = f2tf(v.x); Hs[r][q*4+1] = f2tf(v.y);
            Hs[r][q*4+2] = f2tf(v.z); Hs[r][q*4+3] = f2tf(v.w);
        }
#pragma unroll
        for (int gt = 0; gt < 3; ++gt) {
#pragma unroll
            for (int it = 0; it < 2; ++it) {     // W gate tile 64x32
                int slot = tid + it * 256;
                int r = slot >> 3, q = slot & 7;
                float4 v = *(const float4*)(Wd + (size_t)(gt * 256 + j0 + r) * HD + k0 + q * 4);
                Ws[gt][r][q*4+0] = f2tf(v.x); Ws[gt][r][q*4+1] = f2tf(v.y);
                Ws[gt][r][q*4+2] = f2tf(v.z); Ws[gt][r][q*4+3] = f2tf(v.w);
            }
        }
        __syncthreads();
#pragma unroll
        for (int ks = 0; ks < 4; ++ks) {
            int kb = ks * 8;
            int br = wm * 16;
            unsigned a0 = Hs[br + g    ][kb + c    ];
            unsigned a1 = Hs[br + g + 8][kb + c    ];
            unsigned a2 = Hs[br + g    ][kb + c + 4];
            unsigned a3 = Hs[br + g + 8][kb + c + 4];
#pragma unroll
            for (int gt = 0; gt < 3; ++gt) {
#pragma unroll
                for (int nt = 0; nt < 4; ++nt) {
                    int bn = wn * 32 + nt * 8 + g;
                    unsigned b0 = Ws[gt][bn][kb + c];
                    unsigned b1 = Ws[gt][bn][kb + c + 4];
                    mma8(acc[gt][nt], a0, a1, a2, a3, b0, b1);
                }
            }
        }
        __syncthreads();
    }

    // ---- gate math epilogue ----
    bool is64 = false;
    if (tok) is64 = (tok[1] == 0) & (tok[3] == 0) & (tok[5] == 0) & (tok[7] == 0);

#pragma unroll
    for (int half = 0; half < 2; ++half) {
        int r = n0 + wm * 16 + g + half * 8;
        if (r >= N) continue;
        const float* gxrow;
        if (tok) {
            int ti = r * T + teff;
            int tv = is64 ? tok[2 * (size_t)ti] : tok[ti];
            gxrow = PV + ((size_t)d * VOCAB + tv) * G3;
        } else {
            gxrow = GX + ((size_t)d * N * T + (size_t)r * T + teff) * G3;
        }
        const float* hrow = Hin  + (size_t)(d * N + r) * HD;
        float*       orow = Hout + (size_t)(d * N + r) * HD;
#pragma unroll
        for (int nt = 0; nt < 4; ++nt) {
            int cc = j0 + wn * 32 + nt * 8 + 2 * c;
            float2 gr  = *(const float2*)(gxrow + cc);
            float2 gz  = *(const float2*)(gxrow + 256 + cc);
            float2 gn  = *(const float2*)(gxrow + 512 + cc);
            float2 br2 = *(const float2*)(bhh + (size_t)d * G3 + cc);
            float2 bz2 = *(const float2*)(bhh + (size_t)d * G3 + 256 + cc);
            float2 bn2 = *(const float2*)(bhh + (size_t)d * G3 + 512 + cc);
            float2 h2  = *(const float2*)(hrow + cc);

            float aR0 = acc[0][nt][half * 2 + 0], aR1 = acc[0][nt][half * 2 + 1];
            float aZ0 = acc[1][nt][half * 2 + 0], aZ1 = acc[1][nt][half * 2 + 1];
            float aN0 = acc[2][nt][half * 2 + 0], aN1 = acc[2][nt][half * 2 + 1];

            float r0 = sigm(gr.x + aR0 + br2.x);
            float r1 = sigm(gr.y + aR1 + br2.y);
            float z0 = sigm(gz.x + aZ0 + bz2.x);
            float z1 = sigm(gz.y + aZ1 + bz2.y);
            float n0v = tanhf(gn.x + r0 * (aN0 + bn2.x));
            float n1v = tanhf(gn.y + r1 * (aN1 + bn2.y));

            float2 o;
            o.x = (1.f - z0) * n0v + z0 * h2.x;
            o.y = (1.f - z1) * n1v + z1 * h2.y;
            *(float2*)(orow + cc) = o;
        }
    }
}

// ---------------- sum forward+backward final hidden ----------------
__global__ void sum_dirs(const float* __restrict__ Hf, float* __restrict__ out, int N)
{
    int i = blockIdx.x * 256 + threadIdx.x;
    if (i < N * HD) out[i] = Hf[i] + Hf[(size_t)N * HD + i];
}

// ---------------- FC head: Linear(256->128) -> SELU -> Linear(128->1) ----------------
__global__ void fc_head(const float* __restrict__ X,
                        const float* __restrict__ W1, const float* __restrict__ b1,
                        const float* __restrict__ W2, const float* __restrict__ b2,
                        float* __restrict__ out)
{
    int row = blockIdx.x;
    int h = threadIdx.x;  // 128 threads
    const float* x = X + (size_t)row * HD;
    const float* w = W1 + (size_t)h * HD;
    float s = 0.f;
#pragma unroll 8
    for (int k = 0; k < HD; k += 4) {
        float4 xv = *(const float4*)(x + k);
        float4 wv = *(const float4*)(w + k);
        s += xv.x * wv.x + xv.y * wv.y + xv.z * wv.z + xv.w * wv.w;
    }
    s += b1[h];
    const float SC = 1.0507009873554805f, AL = 1.6732632423543772f;
    float selu = SC * (s > 0.f ? s : AL * expm1f(s));
    float v = selu * W2[h];
    __shared__ float red[128];
    red[h] = v; __syncthreads();
    for (int st = 64; st > 0; st >>= 1) {
        if (h < st) red[h] += red[h + st];
        __syncthreads();
    }
    if (h == 0) out[row] = red[0] + b2[0];
}

// ---------------- launch ----------------
extern "C" void kernel_launch(void* const* d_in, const int* in_sizes, int n_in,
                              void* d_out, int out_size)
{
    const int*   tok   = (const int*)  d_in[0];
    const float* emb   = (const float*)d_in[1];
    const float* wWih  = (const float*)d_in[2];
    const float* wWhh  = (const float*)d_in[3];
    const float* wbih  = (const float*)d_in[4];
    const float* wbhh  = (const float*)d_in[5];
    const float* sWih  = (const float*)d_in[6];
    const float* sWhh  = (const float*)d_in[7];
    const float* sbih  = (const float*)d_in[8];
    const float* sbhh  = (const float*)d_in[9];
    const float* rWih  = (const float*)d_in[10];
    const float* rWhh  = (const float*)d_in[11];
    const float* rbih  = (const float*)d_in[12];
    const float* rbhh  = (const float*)d_in[13];
    const float* rfcW1 = (const float*)d_in[14];
    const float* rfcb1 = (const float*)d_in[15];
    const float* rfcW2 = (const float*)d_in[16];
    const float* rfcb2 = (const float*)d_in[17];
    const float* pfcW1 = (const float*)d_in[18];
    const float* pfcb1 = (const float*)d_in[19];
    const float* pfcW2 = (const float*)d_in[20];
    const float* pfcb2 = (const float*)d_in[21];
    float* out = (float*)d_out;

    float *pv, *gxs, *gxr, *hwB, *hsB, *hrB, *xs, *xr, *xb;
    cudaGetSymbolAddress((void**)&pv,  g_PV);
    cudaGetSymbolAddress((void**)&gxs, g_GXs);
    cudaGetSymbolAddress((void**)&gxr, g_GXr);
    cudaGetSymbolAddress((void**)&hwB, g_Hw);
    cudaGetSymbolAddress((void**)&hsB, g_Hs);
    cudaGetSymbolAddress((void**)&hrB, g_Hr);
    cudaGetSymbolAddress((void**)&xs,  g_Xs);
    cudaGetSymbolAddress((void**)&xr,  g_Xr);
    cudaGetSymbolAddress((void**)&xb,  g_Xb);

    float* hw[2] = { hwB, hwB + (size_t)2 * NW * HD };
    float* hs[2] = { hsB, hsB + (size_t)2 * NS * HD };
    float* hr[2] = { hrB, hrB + (size_t)2 * NR * HD };

    // zero initial hidden states
    kzero<<<2048, 256>>>(hw[0], (size_t)2 * NW * HD);
    kzero<<<256,  256>>>(hs[0], (size_t)2 * NS * HD);
    kzero<<<16,   256>>>(hr[0], (size_t)2 * NR * HD);

    // project full vocabulary once per direction: PV = emb @ Wih^T + bih
    gemm_proj_mma<<<dim3((VOCAB + 127) / 128, G3 / 64, 2), 256>>>(emb, VOCAB, wWih, wbih, pv);

    // word-level scan (T=32): gx rows fetched from PV via tokens inside the step
    for (int t = 0; t < TW; ++t)
        gru_step_mma<<<dim3(NW / 64, 4, 2), 256>>>(hw[t & 1], hw[(t + 1) & 1],
                                                   wWhh, wbhh, nullptr, pv, tok,
                                                   NW, TW, t);
    sum_dirs<<<(NW * HD) / 256, 256>>>(hw[TW & 1], xs, NW);

    // sentence-level: project + scan (T=16)
    gemm_proj_mma<<<dim3((NW + 127) / 128, G3 / 64, 2), 256>>>(xs, NW, sWih, sbih, gxs);
    for (int t = 0; t < TS; ++t)
        gru_step_mma<<<dim3((NS + 63) / 64, 4, 2), 256>>>(hs[t & 1], hs[(t + 1) & 1],
                                                          sWhh, sbhh, gxs, nullptr, nullptr,
                                                          NS, TS, t);
    sum_dirs<<<(NS * HD) / 256, 256>>>(hs[TS & 1], xr, NS);

    // review-star head on review vectors -> out[8..135]
    fc_head<<<NS, 128>>>(xr, rfcW1, rfcb1, rfcW2, rfcb2, out + NR);

    // review-level (business) biGRU: project + scan (T=16)
    gemm_proj_mma<<<dim3(1, G3 / 64, 2), 256>>>(xr, NS, rWih, rbih, gxr);
    for (int t = 0; t < TR; ++t)
        gru_step_mma<<<dim3(1, 4, 2), 256>>>(hr[t & 1], hr[(t + 1) & 1],
                                             rWhh, rbhh, gxr, nullptr, nullptr,
                                             NR, TR, t);
    sum_dirs<<<(NR * HD) / 256, 256>>>(hr[TR & 1], xb, NR);

    // business head -> out[0..7]
    fc_head<<<NR, 128>>>(xb, pfcW1, pfcb1, pfcW2, pfcb2, out);

    (void)in_sizes; (void)n_in; (void)out_size;
}

// round 3
// speedup vs baseline: 1.9100x; 1.5832x over previous
#include <cuda_runtime.h>
#include <cstdint>

// ---------------- problem constants ----------------
#define HD   256      // hidden / embedding dim
#define G3   768      // 3*H gate dim
#define VOCAB 30000
#define NW   2048     // word-level sequences (B*R*S)
#define TW   32       // word-level timesteps (W)
#define NS   128      // sentence-level sequences (B*R)
#define TS   16       // sentence-level timesteps (S)
#define NR   8        // review-level sequences (B)
#define TR   16       // review-level timesteps (R)

#define SP   36       // smem row stride (mod 32 == 4 -> conflict-free frags)

// ---------------- scratch (static device globals; no runtime alloc) ----------------
__device__ float g_PV [(size_t)2*VOCAB*G3];        // projected vocab per dir
__device__ float g_GXs[(size_t)2*NS*TS*G3];        // sentence-level gx
__device__ float g_GXr[(size_t)2*NR*TR*G3];        // review-level gx
__device__ float g_Hw [2][(size_t)2*NW*HD];        // ping-pong hidden, word
__device__ float g_Hs [2][(size_t)2*NS*HD];        // sentence
__device__ float g_Hr [2][(size_t)2*NR*HD];        // review
__device__ float g_Xs [(size_t)NW*HD];             // sentence vectors (h_f+h_b)
__device__ float g_Xr [(size_t)NS*HD];             // review vectors
__device__ float g_Xb [(size_t)NR*HD];             // business vectors

// ---------------- helpers ----------------
__device__ __forceinline__ float sigm(float x) { return 1.f / (1.f + expf(-x)); }

__device__ __forceinline__ unsigned f2tf(float x) {
    unsigned u;
    asm("cvt.rna.tf32.f32 %0, %1;" : "=r"(u) : "f"(x));
    return u;
}

__device__ __forceinline__ void mma8(float* d,
                                     unsigned a0, unsigned a1, unsigned a2, unsigned a3,
                                     unsigned b0, unsigned b1) {
    asm volatile(
        "mma.sync.aligned.m16n8k8.row.col.f32.tf32.tf32.f32 "
        "{%0,%1,%2,%3},{%4,%5,%6,%7},{%8,%9},{%0,%1,%2,%3};"
        : "+f"(d[0]), "+f"(d[1]), "+f"(d[2]), "+f"(d[3])
        : "r"(a0), "r"(a1), "r"(a2), "r"(a3), "r"(b0), "r"(b1));
}

__global__ void kzero(float* p, size_t n) {
    size_t i = (size_t)blockIdx.x * blockDim.x + threadIdx.x;
    size_t stride = (size_t)gridDim.x * blockDim.x;
    for (; i < n; i += stride) p[i] = 0.f;
}

// ---------------- TF32 GEMM: C[d][M,768] = A[M,256] @ W[d][768,256]^T + bias[d] ----------------
// CTA 128(m) x 128(n), block 256, warps 2m x 4n, warp tile 64x32 (mt=4, nt=4)
// grid: (ceil(M/128), 768/128=6, 2)
__global__ __launch_bounds__(256)
void gemm_proj_mma(const float* __restrict__ A, int M,
                   const float* __restrict__ W, const float* __restrict__ bias,
                   float* __restrict__ C)
{
    int d = blockIdx.z;
    const float* Wd = W    + (size_t)d * G3 * HD;
    const float* bd = bias + (size_t)d * G3;
    float*       Cd = C    + (size_t)d * M * G3;

    int m0 = blockIdx.x * 128;
    int n0 = blockIdx.y * 128;

    __shared__ unsigned As[128][SP];
    __shared__ unsigned Bs[128][SP];

    int tid = threadIdx.x, lane = tid & 31, wid = tid >> 5;
    int wm = wid & 1, wn = wid >> 1;
    int RB = wm * 64, CB = wn * 32;
    int g = lane >> 2, c = lane & 3;

    float acc[4][4][4];
#pragma unroll
    for (int i = 0; i < 4; ++i)
#pragma unroll
        for (int j = 0; j < 4; ++j)
#pragma unroll
            for (int k = 0; k < 4; ++k) acc[i][j][k] = 0.f;

    int lr = tid >> 3, lq = tid & 7;   // loader: row base, quad

    float4 pa[4], pw[4];
#pragma unroll
    for (int it = 0; it < 4; ++it) {
        int r = lr + it * 32;
        pa[it] = make_float4(0.f, 0.f, 0.f, 0.f);
        if (m0 + r < M) pa[it] = *(const float4*)(A + (size_t)(m0 + r) * HD + lq * 4);
        pw[it] = *(const float4*)(Wd + (size_t)(n0 + r) * HD + lq * 4);
    }

    for (int k0i = 0; k0i < 8; ++k0i) {
#pragma unroll
        for (int it = 0; it < 4; ++it) {
            int r = lr + it * 32;
            As[r][lq*4+0] = f2tf(pa[it].x); As[r][lq*4+1] = f2tf(pa[it].y);
            As[r][lq*4+2] = f2tf(pa[it].z); As[r][lq*4+3] = f2tf(pa[it].w);
            Bs[r][lq*4+0] = f2tf(pw[it].x); Bs[r][lq*4+1] = f2tf(pw[it].y);
            Bs[r][lq*4+2] = f2tf(pw[it].z); Bs[r][lq*4+3] = f2tf(pw[it].w);
        }
        __syncthreads();

        if (k0i < 7) {
            int k0 = (k0i + 1) * 32;
#pragma unroll
            for (int it = 0; it < 4; ++it) {
                int r = lr + it * 32;
                pa[it] = make_float4(0.f, 0.f, 0.f, 0.f);
                if (m0 + r < M) pa[it] = *(const float4*)(A + (size_t)(m0 + r) * HD + k0 + lq * 4);
                pw[it] = *(const float4*)(Wd + (size_t)(n0 + r) * HD + k0 + lq * 4);
            }
        }

#pragma unroll
        for (int ks = 0; ks < 4; ++ks) {
            int kb = ks * 8;
            unsigned a[4][4];
#pragma unroll
            for (int mt = 0; mt < 4; ++mt) {
                int br = RB + mt * 16;
                a[mt][0] = As[br + g    ][kb + c    ];
                a[mt][1] = As[br + g + 8][kb + c    ];
                a[mt][2] = As[br + g    ][kb + c + 4];
                a[mt][3] = As[br + g + 8][kb + c + 4];
            }
#pragma unroll
            for (int nt = 0; nt < 4; ++nt) {
                int bn = CB + nt * 8 + g;
                unsigned b0 = Bs[bn][kb + c];
                unsigned b1 = Bs[bn][kb + c + 4];
#pragma unroll
                for (int mt = 0; mt < 4; ++mt)
                    mma8(acc[mt][nt], a[mt][0], a[mt][1], a[mt][2], a[mt][3], b0, b1);
            }
        }
        __syncthreads();
    }

#pragma unroll
    for (int nt = 0; nt < 4; ++nt) {
        int col = n0 + CB + nt * 8 + 2 * c;
        float2 bb = *(const float2*)(bd + col);
#pragma unroll
        for (int mt = 0; mt < 4; ++mt) {
            int row0 = m0 + RB + mt * 16 + g;
            if (row0 < M) {
                float2 o = make_float2(acc[mt][nt][0] + bb.x, acc[mt][nt][1] + bb.y);
                *(float2*)(Cd + (size_t)row0 * G3 + col) = o;
            }
            int row1 = row0 + 8;
            if (row1 < M) {
                float2 o = make_float2(acc[mt][nt][2] + bb.x, acc[mt][nt][3] + bb.y);
                *(float2*)(Cd + (size_t)row1 * G3 + col) = o;
            }
        }
    }
}

// ---------------- fused TF32-MMA GRU step ----------------
// CTA 128 rows x 64 j-cols (x3 gates), block 256, warps 2m x 4n,
// warp tile 64 rows x 16 cols x 3 gates (mt=4, nt=2)
// grid: (ceil(N/128), 4, 2)
__global__ __launch_bounds__(256)
void gru_step_mma(const float* __restrict__ Hin, float* __restrict__ Hout,
                  const float* __restrict__ Whh,   // [2][768][256]
                  const float* __restrict__ bhh,   // [2][768]
                  const float* __restrict__ GX,    // [2][N*T][768] or nullptr
                  const float* __restrict__ PV,    // [2][VOCAB][768] or nullptr
                  const int*   __restrict__ tok,   // word-level tokens or nullptr
                  int N, int T, int t)
{
    int d  = blockIdx.z;
    int n0 = blockIdx.x * 128;
    int j0 = blockIdx.y * 64;
    int teff = d ? (T - 1 - t) : t;

    const float* Wd = Whh + (size_t)d * G3 * HD;

    __shared__ unsigned Hs[128][SP];
    __shared__ unsigned Ws[3][64][SP];

    int tid = threadIdx.x, lane = tid & 31, wid = tid >> 5;
    int wm = wid & 1, wn = wid >> 1;
    int RB = wm * 64, CB = wn * 16;
    int g = lane >> 2, c = lane & 3;

    float acc[3][4][2][4];
#pragma unroll
    for (int i = 0; i < 3; ++i)
#pragma unroll
        for (int j = 0; j < 4; ++j)
#pragma unroll
            for (int k = 0; k < 2; ++k)
#pragma unroll
                for (int l = 0; l < 4; ++l) acc[i][j][k][l] = 0.f;

    int lr = tid >> 3, lq = tid & 7;     // H loader: rows 0..127 (4 chunks of 32)
    int lr2 = tid >> 3, lq2 = tid & 7;   // W loader: rows 0..63 (2 chunks of 32)

    float4 ph[4], pw[6];
#pragma unroll
    for (int it = 0; it < 4; ++it) {
        int r = lr + it * 32;
        ph[it] = make_float4(0.f, 0.f, 0.f, 0.f);
        if (n0 + r < N) ph[it] = *(const float4*)(Hin + (size_t)(d * N + n0 + r) * HD + lq * 4);
    }
#pragma unroll
    for (int gt = 0; gt < 3; ++gt)
#pragma unroll
        for (int it = 0; it < 2; ++it) {
            int r = lr2 + it * 32;
            if (r < 64)
                pw[gt*2+it] = *(const float4*)(Wd + (size_t)(gt * 256 + j0 + r) * HD + lq2 * 4);
        }

    for (int k0i = 0; k0i < 8; ++k0i) {
#pragma unroll
        for (int it = 0; it < 4; ++it) {
            int r = lr + it * 32;
            Hs[r][lq*4+0] = f2tf(ph[it].x); Hs[r][lq*4+1] = f2tf(ph[it].y);
            Hs[r][lq*4+2] = f2tf(ph[it].z); Hs[r][lq*4+3] = f2tf(ph[it].w);
        }
#pragma unroll
        for (int gt = 0; gt < 3; ++gt)
#pragma unroll
            for (int it = 0; it < 2; ++it) {
                int r = lr2 + it * 32;
                if (r < 64) {
                    float4 v = pw[gt*2+it];
                    Ws[gt][r][lq2*4+0] = f2tf(v.x); Ws[gt][r][lq2*4+1] = f2tf(v.y);
                    Ws[gt][r][lq2*4+2] = f2tf(v.z); Ws[gt][r][lq2*4+3] = f2tf(v.w);
                }
            }
        __syncthreads();

        if (k0i < 7) {
            int k0 = (k0i + 1) * 32;
#pragma unroll
            for (int it = 0; it < 4; ++it) {
                int r = lr + it * 32;
                ph[it] = make_float4(0.f, 0.f, 0.f, 0.f);
                if (n0 + r < N) ph[it] = *(const float4*)(Hin + (size_t)(d * N + n0 + r) * HD + k0 + lq * 4);
            }
#pragma unroll
            for (int gt = 0; gt < 3; ++gt)
#pragma unroll
                for (int it = 0; it < 2; ++it) {
                    int r = lr2 + it * 32;
                    if (r < 64)
                        pw[gt*2+it] = *(const float4*)(Wd + (size_t)(gt * 256 + j0 + r) * HD + k0 + lq2 * 4);
                }
        }

#pragma unroll
        for (int ks = 0; ks < 4; ++ks) {
            int kb = ks * 8;
            unsigned a[4][4];
#pragma unroll
            for (int mt = 0; mt < 4; ++mt) {
                int br = RB + mt * 16;
                a[mt][0] = Hs[br + g    ][kb + c    ];
                a[mt][1] = Hs[br + g + 8][kb + c    ];
                a[mt][2] = Hs[br + g    ][kb + c + 4];
                a[mt][3] = Hs[br + g + 8][kb + c + 4];
            }
#pragma unroll
            for (int gt = 0; gt < 3; ++gt)
#pragma unroll
                for (int nt = 0; nt < 2; ++nt) {
                    int bn = CB + nt * 8 + g;
                    unsigned b0 = Ws[gt][bn][kb + c];
                    unsigned b1 = Ws[gt][bn][kb + c + 4];
#pragma unroll
                    for (int mt = 0; mt < 4; ++mt)
                        mma8(acc[gt][mt][nt], a[mt][0], a[mt][1], a[mt][2], a[mt][3], b0, b1);
                }
        }
        __syncthreads();
    }

    // ---- gate math epilogue ----
    bool is64 = false;
    if (tok) is64 = (tok[1] == 0) & (tok[3] == 0) & (tok[5] == 0) & (tok[7] == 0);

#pragma unroll
    for (int mt = 0; mt < 4; ++mt) {
#pragma unroll
        for (int half = 0; half < 2; ++half) {
            int r = n0 + RB + mt * 16 + g + half * 8;
            if (r >= N) continue;
            const float* gxrow;
            if (tok) {
                int ti = r * T + teff;
                int tv = is64 ? tok[2 * (size_t)ti] : tok[ti];
                gxrow = PV + ((size_t)d * VOCAB + tv) * G3;
            } else {
                gxrow = GX + ((size_t)d * N * T + (size_t)r * T + teff) * G3;
            }
            const float* hrow = Hin  + (size_t)(d * N + r) * HD;
            float*       orow = Hout + (size_t)(d * N + r) * HD;
#pragma unroll
            for (int nt = 0; nt < 2; ++nt) {
                int cc = j0 + CB + nt * 8 + 2 * c;
                float2 gr  = *(const float2*)(gxrow + cc);
                float2 gz  = *(const float2*)(gxrow + 256 + cc);
                float2 gn  = *(const float2*)(gxrow + 512 + cc);
                float2 br2 = *(const float2*)(bhh + (size_t)d * G3 + cc);
                float2 bz2 = *(const float2*)(bhh + (size_t)d * G3 + 256 + cc);
                float2 bn2 = *(const float2*)(bhh + (size_t)d * G3 + 512 + cc);
                float2 h2  = *(const float2*)(hrow + cc);

                float aR0 = acc[0][mt][nt][half * 2 + 0], aR1 = acc[0][mt][nt][half * 2 + 1];
                float aZ0 = acc[1][mt][nt][half * 2 + 0], aZ1 = acc[1][mt][nt][half * 2 + 1];
                float aN0 = acc[2][mt][nt][half * 2 + 0], aN1 = acc[2][mt][nt][half * 2 + 1];

                float r0 = sigm(gr.x + aR0 + br2.x);
                float r1 = sigm(gr.y + aR1 + br2.y);
                float z0 = sigm(gz.x + aZ0 + bz2.x);
                float z1 = sigm(gz.y + aZ1 + bz2.y);
                float n0v = tanhf(gn.x + r0 * (aN0 + bn2.x));
                float n1v = tanhf(gn.y + r1 * (aN1 + bn2.y));

                float2 o;
                o.x = (1.f - z0) * n0v + z0 * h2.x;
                o.y = (1.f - z1) * n1v + z1 * h2.y;
                *(float2*)(orow + cc) = o;
            }
        }
    }
}

// ---------------- sum forward+backward final hidden ----------------
__global__ void sum_dirs(const float* __restrict__ Hf, float* __restrict__ out, int N)
{
    int i = blockIdx.x * 256 + threadIdx.x;
    if (i < N * HD) out[i] = Hf[i] + Hf[(size_t)N * HD + i];
}

// ---------------- FC head: Linear(256->128) -> SELU -> Linear(128->1) ----------------
__global__ void fc_head(const float* __restrict__ X,
                        const float* __restrict__ W1, const float* __restrict__ b1,
                        const float* __restrict__ W2, const float* __restrict__ b2,
                        float* __restrict__ out)
{
    int row = blockIdx.x;
    int h = threadIdx.x;  // 128 threads
    const float* x = X + (size_t)row * HD;
    const float* w = W1 + (size_t)h * HD;
    float s = 0.f;
#pragma unroll 8
    for (int k = 0; k < HD; k += 4) {
        float4 xv = *(const float4*)(x + k);
        float4 wv = *(const float4*)(w + k);
        s += xv.x * wv.x + xv.y * wv.y + xv.z * wv.z + xv.w * wv.w;
    }
    s += b1[h];
    const float SC = 1.0507009873554805f, AL = 1.6732632423543772f;
    float selu = SC * (s > 0.f ? s : AL * expm1f(s));
    float v = selu * W2[h];
    __shared__ float red[128];
    red[h] = v; __syncthreads();
    for (int st = 64; st > 0; st >>= 1) {
        if (h < st) red[h] += red[h + st];
        __syncthreads();
    }
    if (h == 0) out[row] = red[0] + b2[0];
}

// ---------------- launch ----------------
extern "C" void kernel_launch(void* const* d_in, const int* in_sizes, int n_in,
                              void* d_out, int out_size)
{
    const int*   tok   = (const int*)  d_in[0];
    const float* emb   = (const float*)d_in[1];
    const float* wWih  = (const float*)d_in[2];
    const float* wWhh  = (const float*)d_in[3];
    const float* wbih  = (const float*)d_in[4];
    const float* wbhh  = (const float*)d_in[5];
    const float* sWih  = (const float*)d_in[6];
    const float* sWhh  = (const float*)d_in[7];
    const float* sbih  = (const float*)d_in[8];
    const float* sbhh  = (const float*)d_in[9];
    const float* rWih  = (const float*)d_in[10];
    const float* rWhh  = (const float*)d_in[11];
    const float* rbih  = (const float*)d_in[12];
    const float* rbhh  = (const float*)d_in[13];
    const float* rfcW1 = (const float*)d_in[14];
    const float* rfcb1 = (const float*)d_in[15];
    const float* rfcW2 = (const float*)d_in[16];
    const float* rfcb2 = (const float*)d_in[17];
    const float* pfcW1 = (const float*)d_in[18];
    const float* pfcb1 = (const float*)d_in[19];
    const float* pfcW2 = (const float*)d_in[20];
    const float* pfcb2 = (const float*)d_in[21];
    float* out = (float*)d_out;

    float *pv, *gxs, *gxr, *hwB, *hsB, *hrB, *xs, *xr, *xb;
    cudaGetSymbolAddress((void**)&pv,  g_PV);
    cudaGetSymbolAddress((void**)&gxs, g_GXs);
    cudaGetSymbolAddress((void**)&gxr, g_GXr);
    cudaGetSymbolAddress((void**)&hwB, g_Hw);
    cudaGetSymbolAddress((void**)&hsB, g_Hs);
    cudaGetSymbolAddress((void**)&hrB, g_Hr);
    cudaGetSymbolAddress((void**)&xs,  g_Xs);
    cudaGetSymbolAddress((void**)&xr,  g_Xr);
    cudaGetSymbolAddress((void**)&xb,  g_Xb);

    float* hw[2] = { hwB, hwB + (size_t)2 * NW * HD };
    float* hs[2] = { hsB, hsB + (size_t)2 * NS * HD };
    float* hr[2] = { hrB, hrB + (size_t)2 * NR * HD };

    // zero initial hidden states
    kzero<<<2048, 256>>>(hw[0], (size_t)2 * NW * HD);
    kzero<<<256,  256>>>(hs[0], (size_t)2 * NS * HD);
    kzero<<<16,   256>>>(hr[0], (size_t)2 * NR * HD);

    // project full vocabulary once per direction: PV = emb @ Wih^T + bih
    gemm_proj_mma<<<dim3((VOCAB + 127) / 128, G3 / 128, 2), 256>>>(emb, VOCAB, wWih, wbih, pv);

    // word-level scan (T=32): gx rows fetched from PV via tokens inside the step
    for (int t = 0; t < TW; ++t)
        gru_step_mma<<<dim3(NW / 128, 4, 2), 256>>>(hw[t & 1], hw[(t + 1) & 1],
                                                    wWhh, wbhh, nullptr, pv, tok,
                                                    NW, TW, t);
    sum_dirs<<<(NW * HD) / 256, 256>>>(hw[TW & 1], xs, NW);

    // sentence-level: project + scan (T=16)
    gemm_proj_mma<<<dim3((NW + 127) / 128, G3 / 128, 2), 256>>>(xs, NW, sWih, sbih, gxs);
    for (int t = 0; t < TS; ++t)
        gru_step_mma<<<dim3((NS + 127) / 128, 4, 2), 256>>>(hs[t & 1], hs[(t + 1) & 1],
                                                            sWhh, sbhh, gxs, nullptr, nullptr,
                                                            NS, TS, t);
    sum_dirs<<<(NS * HD) / 256, 256>>>(hs[TS & 1], xr, NS);

    // review-star head on review vectors -> out[8..135]
    fc_head<<<NS, 128>>>(xr, rfcW1, rfcb1, rfcW2, rfcb2, out + NR);

    // review-level (business) biGRU: project + scan (T=16)
    gemm_proj_mma<<<dim3(1, G3 / 128, 2), 256>>>(xr, NS, rWih, rbih, gxr);
    for (int t = 0; t < TR; ++t)
        gru_step_mma<<<dim3(1, 4, 2), 256>>>(hr[t & 1], hr[(t + 1) & 1],
                                             rWhh, rbhh, gxr, nullptr, nullptr,
                                             NR, TR, t);
    sum_dirs<<<(NR * HD) / 256, 256>>>(hr[TR & 1], xb, NR);

    // business head -> out[0..7]
    fc_head<<<NR, 128>>>(xb, pfcW1, pfcb1, pfcW2, pfcb2, out);

    (void)in_sizes; (void)n_in; (void)out_size;
}

// round 4
// speedup vs baseline: 1.9784x; 1.0358x over previous
#include <cuda_runtime.h>
#include <cstdint>

// ---------------- problem constants ----------------
#define HD   256      // hidden / embedding dim
#define G3   768      // 3*H gate dim
#define VOCAB 30000
#define NW   2048     // word-level sequences (B*R*S)
#define TW   32       // word-level timesteps (W)
#define NS   128      // sentence-level sequences (B*R)
#define TS   16       // sentence-level timesteps (S)
#define NR   8        // review-level sequences (B)
#define TR   16       // review-level timesteps (R)

#define SP   36       // smem row stride (mod 32 == 4 -> conflict-free frags)
#define WSP  260      // resident-W row stride (mod 32 == 4)

// dynamic smem for scan kernel: Wres[3*32*260] + Hs[256*36] (unsigned words)
#define SCAN_SMEM_WORDS (3*32*WSP + 256*SP)
#define SCAN_SMEM_BYTES (SCAN_SMEM_WORDS * 4)

// ---------------- scratch (static device globals; no runtime alloc) ----------------
__device__ float g_PV [(size_t)2*VOCAB*G3];        // projected vocab per dir
__device__ float g_GXs[(size_t)2*NS*TS*G3];        // sentence-level gx
__device__ float g_GXr[(size_t)2*NR*TR*G3];        // review-level gx
__device__ float g_Hw [2][(size_t)2*NW*HD];        // ping-pong hidden, word
__device__ float g_Hs [2][(size_t)2*NS*HD];        // sentence
__device__ float g_Hr [2][(size_t)2*NR*HD];        // review
__device__ float g_Xs [(size_t)NW*HD];             // sentence vectors (h_f+h_b)
__device__ float g_Xr [(size_t)NS*HD];             // review vectors
__device__ float g_Xb [(size_t)NR*HD];             // business vectors

// grid-barrier state (one set per scan)
__device__ unsigned g_cnt[4];
__device__ unsigned g_phase[4];

// ---------------- helpers ----------------
__device__ __forceinline__ float sigm(float x) { return 1.f / (1.f + expf(-x)); }

__device__ __forceinline__ unsigned f2tf(float x) {
    unsigned u;
    asm("cvt.rna.tf32.f32 %0, %1;" : "=r"(u) : "f"(x));
    return u;
}

__device__ __forceinline__ void mma8(float* d,
                                     unsigned a0, unsigned a1, unsigned a2, unsigned a3,
                                     unsigned b0, unsigned b1) {
    asm volatile(
        "mma.sync.aligned.m16n8k8.row.col.f32.tf32.tf32.f32 "
        "{%0,%1,%2,%3},{%4,%5,%6,%7},{%8,%9},{%0,%1,%2,%3};"
        : "+f"(d[0]), "+f"(d[1]), "+f"(d[2]), "+f"(d[3])
        : "r"(a0), "r"(a1), "r"(a2), "r"(a3), "r"(b0), "r"(b1));
}

__global__ void kinit_bar() {
    if (threadIdx.x < 4) { g_cnt[threadIdx.x] = 0; g_phase[threadIdx.x] = 0; }
}

__global__ void kzero(float* p, size_t n) {
    size_t i = (size_t)blockIdx.x * blockDim.x + threadIdx.x;
    size_t stride = (size_t)gridDim.x * blockDim.x;
    for (; i < n; i += stride) p[i] = 0.f;
}

// software grid barrier: all nCTA blocks must be co-resident
__device__ __forceinline__ void gbar(int id, unsigned nCTA, unsigned target) {
    __syncthreads();
    if (threadIdx.x == 0) {
        __threadfence();
        unsigned old = atomicAdd(&g_cnt[id], 1u);
        if (old == nCTA - 1u) {
            g_cnt[id] = 0u;
            __threadfence();
            atomicExch(&g_phase[id], target);
        } else {
            while (atomicAdd(&g_phase[id], 0u) < target) __nanosleep(64);
        }
        __threadfence();
    }
    __syncthreads();
}

// ---------------- TF32 GEMM: C[d][M,768] = A[M,256] @ W[d][768,256]^T + bias[d] ----------------
// CTA 128(m) x 64(n), block 256, warps 4m x 2n, warp tile 32x32 (mt=2, nt=4)
// grid: (ceil(M/128), 768/64=12, 2)
__global__ __launch_bounds__(256)
void gemm_proj_mma(const float* __restrict__ A, int M,
                   const float* __restrict__ W, const float* __restrict__ bias,
                   float* __restrict__ C)
{
    int d = blockIdx.z;
    const float* Wd = W    + (size_t)d * G3 * HD;
    const float* bd = bias + (size_t)d * G3;
    float*       Cd = C    + (size_t)d * M * G3;

    int m0 = blockIdx.x * 128;
    int n0 = blockIdx.y * 64;

    __shared__ unsigned As[128][SP];
    __shared__ unsigned Bs[64][SP];

    int tid = threadIdx.x, lane = tid & 31, wid = tid >> 5;
    int wm = wid & 3, wn = wid >> 2;
    int RB = wm * 32, CB = wn * 32;
    int g = lane >> 2, c = lane & 3;

    float acc[2][4][4];
#pragma unroll
    for (int i = 0; i < 2; ++i)
#pragma unroll
        for (int j = 0; j < 4; ++j)
#pragma unroll
            for (int k = 0; k < 4; ++k) acc[i][j][k] = 0.f;

    int lr = tid >> 3, lq = tid & 7;

    float4 pa[4], pw[2];
#pragma unroll
    for (int it = 0; it < 4; ++it) {
        int r = lr + it * 32;
        pa[it] = make_float4(0.f, 0.f, 0.f, 0.f);
        if (m0 + r < M) pa[it] = *(const float4*)(A + (size_t)(m0 + r) * HD + lq * 4);
    }
#pragma unroll
    for (int it = 0; it < 2; ++it) {
        int r = lr + it * 32;
        pw[it] = *(const float4*)(Wd + (size_t)(n0 + r) * HD + lq * 4);
    }

    for (int k0i = 0; k0i < 8; ++k0i) {
#pragma unroll
        for (int it = 0; it < 4; ++it) {
            int r = lr + it * 32;
            As[r][lq*4+0] = f2tf(pa[it].x); As[r][lq*4+1] = f2tf(pa[it].y);
            As[r][lq*4+2] = f2tf(pa[it].z); As[r][lq*4+3] = f2tf(pa[it].w);
        }
#pragma unroll
        for (int it = 0; it < 2; ++it) {
            int r = lr + it * 32;
            Bs[r][lq*4+0] = f2tf(pw[it].x); Bs[r][lq*4+1] = f2tf(pw[it].y);
            Bs[r][lq*4+2] = f2tf(pw[it].z); Bs[r][lq*4+3] = f2tf(pw[it].w);
        }
        __syncthreads();

        if (k0i < 7) {
            int k0 = (k0i + 1) * 32;
#pragma unroll
            for (int it = 0; it < 4; ++it) {
                int r = lr + it * 32;
                pa[it] = make_float4(0.f, 0.f, 0.f, 0.f);
                if (m0 + r < M) pa[it] = *(const float4*)(A + (size_t)(m0 + r) * HD + k0 + lq * 4);
            }
#pragma unroll
            for (int it = 0; it < 2; ++it) {
                int r = lr + it * 32;
                pw[it] = *(const float4*)(Wd + (size_t)(n0 + r) * HD + k0 + lq * 4);
            }
        }

#pragma unroll
        for (int ks = 0; ks < 4; ++ks) {
            int kb = ks * 8;
            unsigned a[2][4];
#pragma unroll
            for (int mt = 0; mt < 2; ++mt) {
                int br = RB + mt * 16;
                a[mt][0] = As[br + g    ][kb + c    ];
                a[mt][1] = As[br + g + 8][kb + c    ];
                a[mt][2] = As[br + g    ][kb + c + 4];
                a[mt][3] = As[br + g + 8][kb + c + 4];
            }
#pragma unroll
            for (int nt = 0; nt < 4; ++nt) {
                int bn = CB + nt * 8 + g;
                unsigned b0 = Bs[bn][kb + c];
                unsigned b1 = Bs[bn][kb + c + 4];
#pragma unroll
                for (int mt = 0; mt < 2; ++mt)
                    mma8(acc[mt][nt], a[mt][0], a[mt][1], a[mt][2], a[mt][3], b0, b1);
            }
        }
        __syncthreads();
    }

#pragma unroll
    for (int nt = 0; nt < 4; ++nt) {
        int col = n0 + CB + nt * 8 + 2 * c;
        float2 bb = *(const float2*)(bd + col);
#pragma unroll
        for (int mt = 0; mt < 2; ++mt) {
            int row0 = m0 + RB + mt * 16 + g;
            if (row0 < M) {
                float2 o = make_float2(acc[mt][nt][0] + bb.x, acc[mt][nt][1] + bb.y);
                *(float2*)(Cd + (size_t)row0 * G3 + col) = o;
            }
            int row1 = row0 + 8;
            if (row1 < M) {
                float2 o = make_float2(acc[mt][nt][2] + bb.x, acc[mt][nt][3] + bb.y);
                *(float2*)(Cd + (size_t)row1 * G3 + col) = o;
            }
        }
    }
}

// ---------------- persistent fused GRU scan (all T steps in one launch) ----------------
// CTA tile: 256 rows x 32 j-cols x 3 gates. Whh slice resident in smem for all steps.
// grid: (ceil(N/256), 8, 2); all CTAs co-resident (<=148); grid barrier per step.
// warps 4m x 2n; warp tile 64 rows x 16 j x 3 gates (mt=4, nt=2)
__global__ __launch_bounds__(256)
void gru_scan(float* __restrict__ H0, float* __restrict__ H1,
              const float* __restrict__ Whh,   // [2][768][256]
              const float* __restrict__ bhh,   // [2][768]
              const float* __restrict__ GX,    // [2][N*T][768] or nullptr
              const float* __restrict__ PV,    // [2][VOCAB][768] or nullptr
              const int*   __restrict__ tok,   // tokens or nullptr
              int N, int T, int barId, unsigned nCTA)
{
    extern __shared__ unsigned smem[];
    unsigned* Wres = smem;                       // [3][32][WSP]
    unsigned (*Hsm)[SP] = (unsigned(*)[SP])(smem + 3 * 32 * WSP);  // [256][SP]

    int d  = blockIdx.z;
    int n0 = blockIdx.x * 256;
    int j0 = blockIdx.y * 32;

    const float* Wd = Whh + (size_t)d * G3 * HD;

    int tid = threadIdx.x, lane = tid & 31, wid = tid >> 5;
    int wm = wid & 3, wn = wid >> 2;
    int RB = wm * 64, CB = wn * 16;
    int g = lane >> 2, c = lane & 3;

    // ---- load resident W slice: rows (gate gt, j) for j in [j0, j0+32) ----
    for (int idx = tid; idx < 96 * 64; idx += 256) {
        int row = idx >> 6;          // 0..95 : gt*32 + j
        int c4  = idx & 63;          // float4 index within 256 cols
        int gt = row >> 5, j = row & 31;
        float4 v = *(const float4*)(Wd + (size_t)(gt * 256 + j0 + j) * HD + c4 * 4);
        unsigned* wr = Wres + (size_t)row * WSP + c4 * 4;
        wr[0] = f2tf(v.x); wr[1] = f2tf(v.y); wr[2] = f2tf(v.z); wr[3] = f2tf(v.w);
    }
    __syncthreads();

    // gate biases for this thread's columns (constant across steps)
    bool is64 = false;
    if (tok) is64 = (tok[1] == 0) & (tok[3] == 0) & (tok[5] == 0) & (tok[7] == 0);

    int lr = tid >> 3, lq = tid & 7;

    for (int t = 0; t < T; ++t) {
        const float* Hin  = (t & 1) ? H1 : H0;
        float*       Hout = (t & 1) ? H0 : H1;
        int teff = d ? (T - 1 - t) : t;

        float acc[3][4][2][4];
#pragma unroll
        for (int i = 0; i < 3; ++i)
#pragma unroll
            for (int j = 0; j < 4; ++j)
#pragma unroll
                for (int k = 0; k < 2; ++k)
#pragma unroll
                    for (int l = 0; l < 4; ++l) acc[i][j][k][l] = 0.f;

        float4 ph[8];
#pragma unroll
        for (int it = 0; it < 8; ++it) {
            int r = lr + it * 32;
            ph[it] = make_float4(0.f, 0.f, 0.f, 0.f);
            if (n0 + r < N)
                ph[it] = *(const float4*)(Hin + (size_t)(d * N + n0 + r) * HD + lq * 4);
        }

        for (int k0i = 0; k0i < 8; ++k0i) {
#pragma unroll
            for (int it = 0; it < 8; ++it) {
                int r = lr + it * 32;
                Hsm[r][lq*4+0] = f2tf(ph[it].x); Hsm[r][lq*4+1] = f2tf(ph[it].y);
                Hsm[r][lq*4+2] = f2tf(ph[it].z); Hsm[r][lq*4+3] = f2tf(ph[it].w);
            }
            __syncthreads();

            if (k0i < 7) {
                int k0 = (k0i + 1) * 32;
#pragma unroll
                for (int it = 0; it < 8; ++it) {
                    int r = lr + it * 32;
                    ph[it] = make_float4(0.f, 0.f, 0.f, 0.f);
                    if (n0 + r < N)
                        ph[it] = *(const float4*)(Hin + (size_t)(d * N + n0 + r) * HD + k0 + lq * 4);
                }
            }

            int kbase = k0i * 32;
#pragma unroll
            for (int ks = 0; ks < 4; ++ks) {
                int kb = ks * 8;
                unsigned a[4][4];
#pragma unroll
                for (int mt = 0; mt < 4; ++mt) {
                    int br = RB + mt * 16;
                    a[mt][0] = Hsm[br + g    ][kb + c    ];
                    a[mt][1] = Hsm[br + g + 8][kb + c    ];
                    a[mt][2] = Hsm[br + g    ][kb + c + 4];
                    a[mt][3] = Hsm[br + g + 8][kb + c + 4];
                }
#pragma unroll
                for (int gt = 0; gt < 3; ++gt)
#pragma unroll
                    for (int nt = 0; nt < 2; ++nt) {
                        int bn = CB + nt * 8 + g;
                        const unsigned* wr = Wres + (size_t)(gt * 32 + bn) * WSP + kbase + kb;
                        unsigned b0 = wr[c];
                        unsigned b1 = wr[c + 4];
#pragma unroll
                        for (int mt = 0; mt < 4; ++mt)
                            mma8(acc[gt][mt][nt], a[mt][0], a[mt][1], a[mt][2], a[mt][3], b0, b1);
                    }
            }
            __syncthreads();
        }

        // ---- gate math epilogue ----
#pragma unroll
        for (int mt = 0; mt < 4; ++mt) {
#pragma unroll
            for (int half = 0; half < 2; ++half) {
                int r = n0 + RB + mt * 16 + g + half * 8;
                if (r >= N) continue;
                const float* gxrow;
                if (tok) {
                    int ti = r * T + teff;
                    int tv = is64 ? tok[2 * (size_t)ti] : tok[ti];
                    gxrow = PV + ((size_t)d * VOCAB + tv) * G3;
                } else {
                    gxrow = GX + ((size_t)d * N * T + (size_t)r * T + teff) * G3;
                }
                const float* hrow = Hin  + (size_t)(d * N + r) * HD;
                float*       orow = Hout + (size_t)(d * N + r) * HD;
#pragma unroll
                for (int nt = 0; nt < 2; ++nt) {
                    int cc = j0 + CB + nt * 8 + 2 * c;
                    float2 gr  = *(const float2*)(gxrow + cc);
                    float2 gz  = *(const float2*)(gxrow + 256 + cc);
                    float2 gn  = *(const float2*)(gxrow + 512 + cc);
                    float2 br2 = *(const float2*)(bhh + (size_t)d * G3 + cc);
                    float2 bz2 = *(const float2*)(bhh + (size_t)d * G3 + 256 + cc);
                    float2 bn2 = *(const float2*)(bhh + (size_t)d * G3 + 512 + cc);
                    float2 h2  = *(const float2*)(hrow + cc);

                    float aR0 = acc[0][mt][nt][half * 2 + 0], aR1 = acc[0][mt][nt][half * 2 + 1];
                    float aZ0 = acc[1][mt][nt][half * 2 + 0], aZ1 = acc[1][mt][nt][half * 2 + 1];
                    float aN0 = acc[2][mt][nt][half * 2 + 0], aN1 = acc[2][mt][nt][half * 2 + 1];

                    float r0 = sigm(gr.x + aR0 + br2.x);
                    float r1 = sigm(gr.y + aR1 + br2.y);
                    float z0 = sigm(gz.x + aZ0 + bz2.x);
                    float z1 = sigm(gz.y + aZ1 + bz2.y);
                    float n0v = tanhf(gn.x + r0 * (aN0 + bn2.x));
                    float n1v = tanhf(gn.y + r1 * (aN1 + bn2.y));

                    float2 o;
                    o.x = (1.f - z0) * n0v + z0 * h2.x;
                    o.y = (1.f - z1) * n1v + z1 * h2.y;
                    *(float2*)(orow + cc) = o;
                }
            }
        }

        gbar(barId, nCTA, (unsigned)(t + 1));
    }
}

// ---------------- sum forward+backward final hidden ----------------
__global__ void sum_dirs(const float* __restrict__ Hf, float* __restrict__ out, int N)
{
    int i = blockIdx.x * 256 + threadIdx.x;
    if (i < N * HD) out[i] = Hf[i] + Hf[(size_t)N * HD + i];
}

// ---------------- FC head: Linear(256->128) -> SELU -> Linear(128->1) ----------------
__global__ void fc_head(const float* __restrict__ X,
                        const float* __restrict__ W1, const float* __restrict__ b1,
                        const float* __restrict__ W2, const float* __restrict__ b2,
                        float* __restrict__ out)
{
    int row = blockIdx.x;
    int h = threadIdx.x;  // 128 threads
    const float* x = X + (size_t)row * HD;
    const float* w = W1 + (size_t)h * HD;
    float s = 0.f;
#pragma unroll 8
    for (int k = 0; k < HD; k += 4) {
        float4 xv = *(const float4*)(x + k);
        float4 wv = *(const float4*)(w + k);
        s += xv.x * wv.x + xv.y * wv.y + xv.z * wv.z + xv.w * wv.w;
    }
    s += b1[h];
    const float SC = 1.0507009873554805f, AL = 1.6732632423543772f;
    float selu = SC * (s > 0.f ? s : AL * expm1f(s));
    float v = selu * W2[h];
    __shared__ float red[128];
    red[h] = v; __syncthreads();
    for (int st = 64; st > 0; st >>= 1) {
        if (h < st) red[h] += red[h + st];
        __syncthreads();
    }
    if (h == 0) out[row] = red[0] + b2[0];
}

// ---------------- launch ----------------
extern "C" void kernel_launch(void* const* d_in, const int* in_sizes, int n_in,
                              void* d_out, int out_size)
{
    const int*   tok   = (const int*)  d_in[0];
    const float* emb   = (const float*)d_in[1];
    const float* wWih  = (const float*)d_in[2];
    const float* wWhh  = (const float*)d_in[3];
    const float* wbih  = (const float*)d_in[4];
    const float* wbhh  = (const float*)d_in[5];
    const float* sWih  = (const float*)d_in[6];
    const float* sWhh  = (const float*)d_in[7];
    const float* sbih  = (const float*)d_in[8];
    const float* sbhh  = (const float*)d_in[9];
    const float* rWih  = (const float*)d_in[10];
    const float* rWhh  = (const float*)d_in[11];
    const float* rbih  = (const float*)d_in[12];
    const float* rbhh  = (const float*)d_in[13];
    const float* rfcW1 = (const float*)d_in[14];
    const float* rfcb1 = (const float*)d_in[15];
    const float* rfcW2 = (const float*)d_in[16];
    const float* rfcb2 = (const float*)d_in[17];
    const float* pfcW1 = (const float*)d_in[18];
    const float* pfcb1 = (const float*)d_in[19];
    const float* pfcW2 = (const float*)d_in[20];
    const float* pfcb2 = (const float*)d_in[21];
    float* out = (float*)d_out;

    static bool attr_set = false;
    if (!attr_set) {
        cudaFuncSetAttribute(gru_scan, cudaFuncAttributeMaxDynamicSharedMemorySize,
                             SCAN_SMEM_BYTES);
        attr_set = true;
    }

    float *pv, *gxs, *gxr, *hwB, *hsB, *hrB, *xs, *xr, *xb;
    cudaGetSymbolAddress((void**)&pv,  g_PV);
    cudaGetSymbolAddress((void**)&gxs, g_GXs);
    cudaGetSymbolAddress((void**)&gxr, g_GXr);
    cudaGetSymbolAddress((void**)&hwB, g_Hw);
    cudaGetSymbolAddress((void**)&hsB, g_Hs);
    cudaGetSymbolAddress((void**)&hrB, g_Hr);
    cudaGetSymbolAddress((void**)&xs,  g_Xs);
    cudaGetSymbolAddress((void**)&xr,  g_Xr);
    cudaGetSymbolAddress((void**)&xb,  g_Xb);

    float* hw1 = hwB + (size_t)2 * NW * HD;
    float* hs1 = hsB + (size_t)2 * NS * HD;
    float* hr1 = hrB + (size_t)2 * NR * HD;

    // init barrier state + zero initial hidden states
    kinit_bar<<<1, 32>>>();
    kzero<<<2048, 256>>>(hwB, (size_t)2 * NW * HD);
    kzero<<<256,  256>>>(hsB, (size_t)2 * NS * HD);
    kzero<<<16,   256>>>(hrB, (size_t)2 * NR * HD);

    // project full vocabulary once per direction: PV = emb @ Wih^T + bih
    gemm_proj_mma<<<dim3((VOCAB + 127) / 128, G3 / 64, 2), 256>>>(emb, VOCAB, wWih, wbih, pv);

    // word-level scan (T=32), persistent: 128 CTAs
    gru_scan<<<dim3(NW / 256, 8, 2), 256, SCAN_SMEM_BYTES>>>(
        hwB, hw1, wWhh, wbhh, nullptr, pv, tok, NW, TW, 0, NW / 256 * 8 * 2);
    sum_dirs<<<(NW * HD) / 256, 256>>>((TW & 1) ? hw1 : hwB, xs, NW);

    // sentence-level: project + persistent scan (T=16), 16 CTAs
    gemm_proj_mma<<<dim3((NW + 127) / 128, G3 / 64, 2), 256>>>(xs, NW, sWih, sbih, gxs);
    gru_scan<<<dim3(1, 8, 2), 256, SCAN_SMEM_BYTES>>>(
        hsB, hs1, sWhh, sbhh, gxs, nullptr, nullptr, NS, TS, 1, 16);
    sum_dirs<<<(NS * HD) / 256, 256>>>((TS & 1) ? hs1 : hsB, xr, NS);

    // review-star head on review vectors -> out[8..135]
    fc_head<<<NS, 128>>>(xr, rfcW1, rfcb1, rfcW2, rfcb2, out + NR);

    // review-level (business) biGRU: project + persistent scan (T=16), 16 CTAs
    gemm_proj_mma<<<dim3(1, G3 / 64, 2), 256>>>(xr, NS, rWih, rbih, gxr);
    gru_scan<<<dim3(1, 8, 2), 256, SCAN_SMEM_BYTES>>>(
        hrB, hr1, rWhh, rbhh, gxr, nullptr, nullptr, NR, TR, 2, 16);
    sum_dirs<<<(NR * HD) / 256, 256>>>((TR & 1) ? hr1 : hrB, xb, NR);

    // business head -> out[0..7]
    fc_head<<<NR, 128>>>(xb, pfcW1, pfcb1, pfcW2, pfcb2, out);

    (void)in_sizes; (void)n_in; (void)out_size;
}

// round 5
// speedup vs baseline: 2.2695x; 1.1471x over previous
#include <cuda_runtime.h>
#include <cstdint>

// ---------------- problem constants ----------------
#define HD   256      // hidden / embedding dim
#define G3   768      // 3*H gate dim
#define VOCAB 30000
#define NW   2048     // word-level sequences (B*R*S)
#define TW   32       // word-level timesteps (W)
#define NS   128      // sentence-level sequences (B*R)
#define TS   16       // sentence-level timesteps (S)
#define NR   8        // review-level sequences (B)
#define TR   16       // review-level timesteps (R)

#define SP   36       // smem row stride (mod 32 == 4 -> conflict-free frags)
#define WSP  260      // resident-W row stride (mod 32 == 4)

// scan smem: Wres[48*WSP] + Hsm[256*SP]  (unsigned words)
#define SCAN_SMEM_WORDS (48*WSP + 256*SP)
#define SCAN_SMEM_BYTES (SCAN_SMEM_WORDS * 4)
// gemm smem: double-buffered As[2][128][SP] + Bs[2][64][SP]
#define GEMM_SMEM_WORDS (2*128*SP + 2*64*SP)
#define GEMM_SMEM_BYTES (GEMM_SMEM_WORDS * 4)

// ---------------- scratch (static device globals; no runtime alloc) ----------------
__device__ float g_PV [(size_t)2*VOCAB*G3];        // projected vocab per dir
__device__ float g_GXs[(size_t)2*NS*TS*G3];        // sentence-level gx
__device__ float g_GXr[(size_t)2*NR*TR*G3];        // review-level gx
__device__ float g_Hw [2][(size_t)2*NW*HD];        // ping-pong hidden, word
__device__ float g_Hs [2][(size_t)2*NS*HD];        // sentence
__device__ float g_Hr [2][(size_t)2*NR*HD];        // review
__device__ float g_Xs [(size_t)NW*HD];             // sentence vectors (h_f+h_b)
__device__ float g_Xr [(size_t)NS*HD];             // review vectors
__device__ float g_Xb [(size_t)NR*HD];             // business vectors

// grid-barrier state (one set per scan)
__device__ unsigned g_cnt[4];
__device__ volatile unsigned g_phase[4];

// ---------------- helpers ----------------
__device__ __forceinline__ float fsigm(float x) {
    float e = __expf(-x);
    return __fdividef(1.f, 1.f + e);
}
__device__ __forceinline__ float ftanh(float x) {
    float ax = fabsf(x);
    float e = __expf(-2.f * ax);
    float r = __fdividef(1.f - e, 1.f + e);
    return copysignf(r, x);
}

__device__ __forceinline__ unsigned f2tf(float x) {
    unsigned u;
    asm("cvt.rna.tf32.f32 %0, %1;" : "=r"(u) : "f"(x));
    return u;
}

__device__ __forceinline__ void mma8(float* d,
                                     unsigned a0, unsigned a1, unsigned a2, unsigned a3,
                                     unsigned b0, unsigned b1) {
    asm volatile(
        "mma.sync.aligned.m16n8k8.row.col.f32.tf32.tf32.f32 "
        "{%0,%1,%2,%3},{%4,%5,%6,%7},{%8,%9},{%0,%1,%2,%3};"
        : "+f"(d[0]), "+f"(d[1]), "+f"(d[2]), "+f"(d[3])
        : "r"(a0), "r"(a1), "r"(a2), "r"(a3), "r"(b0), "r"(b1));
}

__global__ void kinit_bar() {
    if (threadIdx.x < 4) { g_cnt[threadIdx.x] = 0; g_phase[threadIdx.x] = 0; }
}

__global__ void kzero(float* p, size_t n) {
    size_t i = (size_t)blockIdx.x * blockDim.x + threadIdx.x;
    size_t stride = (size_t)gridDim.x * blockDim.x;
    for (; i < n; i += stride) p[i] = 0.f;
}

// software grid barrier: all nCTA blocks must be co-resident
__device__ __forceinline__ void gbar(int id, unsigned nCTA, unsigned target) {
    __syncthreads();
    if (threadIdx.x == 0) {
        __threadfence();
        unsigned old = atomicAdd(&g_cnt[id], 1u);
        if (old == nCTA - 1u) {
            g_cnt[id] = 0u;
            __threadfence();
            g_phase[id] = target;
        } else {
            while (g_phase[id] < target) __nanosleep(64);
        }
        __threadfence();
    }
    __syncthreads();
}

// ---------------- TF32 GEMM: C[d][M,768] = A[M,256] @ W[d][768,256]^T + bias[d] ----------------
// CTA 128(m) x 64(n), block 256, warps 4m x 2n, warp tile 32x32 (mt=2, nt=4)
// double-buffered smem, one sync per k-chunk. grid: (ceil(M/128), 12, 2)
__global__ __launch_bounds__(256, 2)
void gemm_proj_mma(const float* __restrict__ A, int M,
                   const float* __restrict__ W, const float* __restrict__ bias,
                   float* __restrict__ C)
{
    extern __shared__ unsigned gsm[];
    unsigned* As = gsm;                  // [2][128][SP]
    unsigned* Bs = gsm + 2 * 128 * SP;   // [2][64][SP]

    int d = blockIdx.z;
    const float* Wd = W    + (size_t)d * G3 * HD;
    const float* bd = bias + (size_t)d * G3;
    float*       Cd = C    + (size_t)d * M * G3;

    int m0 = blockIdx.x * 128;
    int n0 = blockIdx.y * 64;

    int tid = threadIdx.x, lane = tid & 31, wid = tid >> 5;
    int wm = wid & 3, wn = wid >> 2;
    int RB = wm * 32, CB = wn * 32;
    int g = lane >> 2, c = lane & 3;

    float acc[2][4][4];
#pragma unroll
    for (int i = 0; i < 2; ++i)
#pragma unroll
        for (int j = 0; j < 4; ++j)
#pragma unroll
            for (int k = 0; k < 4; ++k) acc[i][j][k] = 0.f;

    int lr = tid >> 3, lq = tid & 7;

    float4 pa[4], pw[2];
#pragma unroll
    for (int it = 0; it < 4; ++it) {
        int r = lr + it * 32;
        pa[it] = make_float4(0.f, 0.f, 0.f, 0.f);
        if (m0 + r < M) pa[it] = *(const float4*)(A + (size_t)(m0 + r) * HD + lq * 4);
    }
#pragma unroll
    for (int it = 0; it < 2; ++it) {
        int r = lr + it * 32;
        pw[it] = *(const float4*)(Wd + (size_t)(n0 + r) * HD + lq * 4);
    }
    // store chunk 0 into buffer 0
#pragma unroll
    for (int it = 0; it < 4; ++it) {
        int r = lr + it * 32;
        unsigned* a = As + (size_t)r * SP + lq * 4;
        a[0] = f2tf(pa[it].x); a[1] = f2tf(pa[it].y); a[2] = f2tf(pa[it].z); a[3] = f2tf(pa[it].w);
    }
#pragma unroll
    for (int it = 0; it < 2; ++it) {
        int r = lr + it * 32;
        unsigned* b = Bs + (size_t)r * SP + lq * 4;
        b[0] = f2tf(pw[it].x); b[1] = f2tf(pw[it].y); b[2] = f2tf(pw[it].z); b[3] = f2tf(pw[it].w);
    }
    __syncthreads();

    for (int k0i = 0; k0i < 8; ++k0i) {
        int cur = k0i & 1;
        if (k0i < 7) {
            int k0 = (k0i + 1) * 32;
#pragma unroll
            for (int it = 0; it < 4; ++it) {
                int r = lr + it * 32;
                pa[it] = make_float4(0.f, 0.f, 0.f, 0.f);
                if (m0 + r < M) pa[it] = *(const float4*)(A + (size_t)(m0 + r) * HD + k0 + lq * 4);
            }
#pragma unroll
            for (int it = 0; it < 2; ++it) {
                int r = lr + it * 32;
                pw[it] = *(const float4*)(Wd + (size_t)(n0 + r) * HD + k0 + lq * 4);
            }
        }

        const unsigned* Ac = As + (size_t)cur * 128 * SP;
        const unsigned* Bc = Bs + (size_t)cur * 64 * SP;
#pragma unroll
        for (int ks = 0; ks < 4; ++ks) {
            int kb = ks * 8;
            unsigned a[2][4];
#pragma unroll
            for (int mt = 0; mt < 2; ++mt) {
                int br = RB + mt * 16;
                a[mt][0] = Ac[(br + g    ) * SP + kb + c    ];
                a[mt][1] = Ac[(br + g + 8) * SP + kb + c    ];
                a[mt][2] = Ac[(br + g    ) * SP + kb + c + 4];
                a[mt][3] = Ac[(br + g + 8) * SP + kb + c + 4];
            }
#pragma unroll
            for (int nt = 0; nt < 4; ++nt) {
                int bn = CB + nt * 8 + g;
                unsigned b0 = Bc[bn * SP + kb + c];
                unsigned b1 = Bc[bn * SP + kb + c + 4];
#pragma unroll
                for (int mt = 0; mt < 2; ++mt)
                    mma8(acc[mt][nt], a[mt][0], a[mt][1], a[mt][2], a[mt][3], b0, b1);
            }
        }

        if (k0i < 7) {
            unsigned* An = As + (size_t)(cur ^ 1) * 128 * SP;
            unsigned* Bn = Bs + (size_t)(cur ^ 1) * 64 * SP;
#pragma unroll
            for (int it = 0; it < 4; ++it) {
                int r = lr + it * 32;
                unsigned* a = An + (size_t)r * SP + lq * 4;
                a[0] = f2tf(pa[it].x); a[1] = f2tf(pa[it].y); a[2] = f2tf(pa[it].z); a[3] = f2tf(pa[it].w);
            }
#pragma unroll
            for (int it = 0; it < 2; ++it) {
                int r = lr + it * 32;
                unsigned* b = Bn + (size_t)r * SP + lq * 4;
                b[0] = f2tf(pw[it].x); b[1] = f2tf(pw[it].y); b[2] = f2tf(pw[it].z); b[3] = f2tf(pw[it].w);
            }
        }
        __syncthreads();
    }

#pragma unroll
    for (int nt = 0; nt < 4; ++nt) {
        int col = n0 + CB + nt * 8 + 2 * c;
        float2 bb = *(const float2*)(bd + col);
#pragma unroll
        for (int mt = 0; mt < 2; ++mt) {
            int row0 = m0 + RB + mt * 16 + g;
            if (row0 < M) {
                float2 o = make_float2(acc[mt][nt][0] + bb.x, acc[mt][nt][1] + bb.y);
                *(float2*)(Cd + (size_t)row0 * G3 + col) = o;
            }
            int row1 = row0 + 8;
            if (row1 < M) {
                float2 o = make_float2(acc[mt][nt][2] + bb.x, acc[mt][nt][3] + bb.y);
                *(float2*)(Cd + (size_t)row1 * G3 + col) = o;
            }
        }
    }
}

// ---------------- persistent fused GRU scan (all T steps in one launch) ----------------
// CTA tile: 256 rows x 16 j-cols x 3 gates; W slice resident in smem (50KB);
// 2 CTAs per SM (launch_bounds(256,2)) for latency hiding.
// grid: (ceil(N/256), 16, 2); grid barrier per step.
// warps 4m x 2n; warp tile 64 rows x 8 j x 3 gates (mt=4)
__global__ __launch_bounds__(256, 2)
void gru_scan(float* __restrict__ H0, float* __restrict__ H1,
              const float* __restrict__ Whh,   // [2][768][256]
              const float* __restrict__ bhh,   // [2][768]
              const float* __restrict__ GX,    // [2][N*T][768] or nullptr
              const float* __restrict__ PV,    // [2][VOCAB][768] or nullptr
              const int*   __restrict__ tok,   // tokens or nullptr
              int N, int T, int barId, unsigned nCTA)
{
    extern __shared__ unsigned smem[];
    unsigned* Wres = smem;                                   // [48][WSP] rows: gt*16+j
    unsigned (*Hsm)[SP] = (unsigned(*)[SP])(smem + 48 * WSP);  // [256][SP]

    int d  = blockIdx.z;
    int n0 = blockIdx.x * 256;
    int j0 = blockIdx.y * 16;

    const float* Wd = Whh + (size_t)d * G3 * HD;

    int tid = threadIdx.x, lane = tid & 31, wid = tid >> 5;
    int wm = wid & 3, wn = wid >> 2;
    int RB = wm * 64, CB = wn * 8;
    int g = lane >> 2, c = lane & 3;

    // ---- load resident W slice: 48 rows (gt*16 + j), 256 cols ----
    for (int idx = tid; idx < 48 * 64; idx += 256) {
        int row = idx >> 6;          // 0..47
        int c4  = idx & 63;
        int gt = row >> 4, j = row & 15;
        float4 v = *(const float4*)(Wd + (size_t)(gt * 256 + j0 + j) * HD + c4 * 4);
        unsigned* wr = Wres + (size_t)row * WSP + c4 * 4;
        wr[0] = f2tf(v.x); wr[1] = f2tf(v.y); wr[2] = f2tf(v.z); wr[3] = f2tf(v.w);
    }
    __syncthreads();

    bool is64 = false;
    if (tok) is64 = (tok[1] == 0) & (tok[3] == 0) & (tok[5] == 0) & (tok[7] == 0);

    int lr = tid >> 3, lq = tid & 7;

    for (int t = 0; t < T; ++t) {
        const float* Hin  = (t & 1) ? H1 : H0;
        float*       Hout = (t & 1) ? H0 : H1;
        int teff = d ? (T - 1 - t) : t;

        float acc[3][4][4];
#pragma unroll
        for (int i = 0; i < 3; ++i)
#pragma unroll
            for (int j = 0; j < 4; ++j)
#pragma unroll
                for (int k = 0; k < 4; ++k) acc[i][j][k] = 0.f;

        // prefetch H chunk 0
        float4 ph[8];
#pragma unroll
        for (int it = 0; it < 8; ++it) {
            int r = lr + it * 32;
            ph[it] = make_float4(0.f, 0.f, 0.f, 0.f);
            if (n0 + r < N)
                ph[it] = *(const float4*)(Hin + (size_t)(d * N + n0 + r) * HD + lq * 4);
        }

        for (int k0i = 0; k0i < 8; ++k0i) {
#pragma unroll
            for (int it = 0; it < 8; ++it) {
                int r = lr + it * 32;
                Hsm[r][lq*4+0] = f2tf(ph[it].x); Hsm[r][lq*4+1] = f2tf(ph[it].y);
                Hsm[r][lq*4+2] = f2tf(ph[it].z); Hsm[r][lq*4+3] = f2tf(ph[it].w);
            }
            __syncthreads();

            if (k0i < 7) {
                int k0 = (k0i + 1) * 32;
#pragma unroll
                for (int it = 0; it < 8; ++it) {
                    int r = lr + it * 32;
                    ph[it] = make_float4(0.f, 0.f, 0.f, 0.f);
                    if (n0 + r < N)
                        ph[it] = *(const float4*)(Hin + (size_t)(d * N + n0 + r) * HD + k0 + lq * 4);
                }
            }

            int kbase = k0i * 32;
#pragma unroll
            for (int ks = 0; ks < 4; ++ks) {
                int kb = ks * 8;
                unsigned a[4][4];
#pragma unroll
                for (int mt = 0; mt < 4; ++mt) {
                    int br = RB + mt * 16;
                    a[mt][0] = Hsm[br + g    ][kb + c    ];
                    a[mt][1] = Hsm[br + g + 8][kb + c    ];
                    a[mt][2] = Hsm[br + g    ][kb + c + 4];
                    a[mt][3] = Hsm[br + g + 8][kb + c + 4];
                }
#pragma unroll
                for (int gt = 0; gt < 3; ++gt) {
                    const unsigned* wr = Wres + (size_t)(gt * 16 + CB + g) * WSP + kbase + kb;
                    unsigned b0 = wr[c];
                    unsigned b1 = wr[c + 4];
#pragma unroll
                    for (int mt = 0; mt < 4; ++mt)
                        mma8(acc[gt][mt], a[mt][0], a[mt][1], a[mt][2], a[mt][3], b0, b1);
                }
            }
            __syncthreads();
        }

        // ---- gate math epilogue (thread covers 2 cols x 8 row-instances) ----
#pragma unroll
        for (int mt = 0; mt < 4; ++mt) {
#pragma unroll
            for (int half = 0; half < 2; ++half) {
                int r = n0 + RB + mt * 16 + g + half * 8;
                if (r >= N) continue;
                const float* gxrow;
                if (tok) {
                    int ti = r * T + teff;
                    int tv = is64 ? tok[2 * (size_t)ti] : tok[ti];
                    gxrow = PV + ((size_t)d * VOCAB + tv) * G3;
                } else {
                    gxrow = GX + ((size_t)d * N * T + (size_t)r * T + teff) * G3;
                }
                const float* hrow = Hin  + (size_t)(d * N + r) * HD;
                float*       orow = Hout + (size_t)(d * N + r) * HD;

                int cc = j0 + CB + 2 * c;
                float2 gr  = *(const float2*)(gxrow + cc);
                float2 gz  = *(const float2*)(gxrow + 256 + cc);
                float2 gn  = *(const float2*)(gxrow + 512 + cc);
                float2 br2 = *(const float2*)(bhh + (size_t)d * G3 + cc);
                float2 bz2 = *(const float2*)(bhh + (size_t)d * G3 + 256 + cc);
                float2 bn2 = *(const float2*)(bhh + (size_t)d * G3 + 512 + cc);
                float2 h2  = *(const float2*)(hrow + cc);

                float aR0 = acc[0][mt][half * 2 + 0], aR1 = acc[0][mt][half * 2 + 1];
                float aZ0 = acc[1][mt][half * 2 + 0], aZ1 = acc[1][mt][half * 2 + 1];
                float aN0 = acc[2][mt][half * 2 + 0], aN1 = acc[2][mt][half * 2 + 1];

                float r0 = fsigm(gr.x + aR0 + br2.x);
                float r1 = fsigm(gr.y + aR1 + br2.y);
                float z0 = fsigm(gz.x + aZ0 + bz2.x);
                float z1 = fsigm(gz.y + aZ1 + bz2.y);
                float n0v = ftanh(gn.x + r0 * (aN0 + bn2.x));
                float n1v = ftanh(gn.y + r1 * (aN1 + bn2.y));

                float2 o;
                o.x = (1.f - z0) * n0v + z0 * h2.x;
                o.y = (1.f - z1) * n1v + z1 * h2.y;
                *(float2*)(orow + cc) = o;
            }
        }

        gbar(barId, nCTA, (unsigned)(t + 1));
    }
}

// ---------------- sum forward+backward final hidden ----------------
__global__ void sum_dirs(const float* __restrict__ Hf, float* __restrict__ out, int N)
{
    int i = blockIdx.x * 256 + threadIdx.x;
    if (i < N * HD) out[i] = Hf[i] + Hf[(size_t)N * HD + i];
}

// ---------------- FC head: Linear(256->128) -> SELU -> Linear(128->1) ----------------
__global__ void fc_head(const float* __restrict__ X,
                        const float* __restrict__ W1, const float* __restrict__ b1,
                        const float* __restrict__ W2, const float* __restrict__ b2,
                        float* __restrict__ out)
{
    int row = blockIdx.x;
    int h = threadIdx.x;  // 128 threads
    const float* x = X + (size_t)row * HD;
    const float* w = W1 + (size_t)h * HD;
    float s = 0.f;
#pragma unroll 8
    for (int k = 0; k < HD; k += 4) {
        float4 xv = *(const float4*)(x + k);
        float4 wv = *(const float4*)(w + k);
        s += xv.x * wv.x + xv.y * wv.y + xv.z * wv.z + xv.w * wv.w;
    }
    s += b1[h];
    const float SC = 1.0507009873554805f, AL = 1.6732632423543772f;
    float selu = SC * (s > 0.f ? s : AL * expm1f(s));
    float v = selu * W2[h];
    __shared__ float red[128];
    red[h] = v; __syncthreads();
    for (int st = 64; st > 0; st >>= 1) {
        if (h < st) red[h] += red[h + st];
        __syncthreads();
    }
    if (h == 0) out[row] = red[0] + b2[0];
}

// ---------------- launch ----------------
extern "C" void kernel_launch(void* const* d_in, const int* in_sizes, int n_in,
                              void* d_out, int out_size)
{
    const int*   tok   = (const int*)  d_in[0];
    const float* emb   = (const float*)d_in[1];
    const float* wWih  = (const float*)d_in[2];
    const float* wWhh  = (const float*)d_in[3];
    const float* wbih  = (const float*)d_in[4];
    const float* wbhh  = (const float*)d_in[5];
    const float* sWih  = (const float*)d_in[6];
    const float* sWhh  = (const float*)d_in[7];
    const float* sbih  = (const float*)d_in[8];
    const float* sbhh  = (const float*)d_in[9];
    const float* rWih  = (const float*)d_in[10];
    const float* rWhh  = (const float*)d_in[11];
    const float* rbih  = (const float*)d_in[12];
    const float* rbhh  = (const float*)d_in[13];
    const float* rfcW1 = (const float*)d_in[14];
    const float* rfcb1 = (const float*)d_in[15];
    const float* rfcW2 = (const float*)d_in[16];
    const float* rfcb2 = (const float*)d_in[17];
    const float* pfcW1 = (const float*)d_in[18];
    const float* pfcb1 = (const float*)d_in[19];
    const float* pfcW2 = (const float*)d_in[20];
    const float* pfcb2 = (const float*)d_in[21];
    float* out = (float*)d_out;

    static bool attr_set = false;
    if (!attr_set) {
        cudaFuncSetAttribute(gru_scan, cudaFuncAttributeMaxDynamicSharedMemorySize,
                             SCAN_SMEM_BYTES);
        cudaFuncSetAttribute(gemm_proj_mma, cudaFuncAttributeMaxDynamicSharedMemorySize,
                             GEMM_SMEM_BYTES);
        attr_set = true;
    }

    float *pv, *gxs, *gxr, *hwB, *hsB, *hrB, *xs, *xr, *xb;
    cudaGetSymbolAddress((void**)&pv,  g_PV);
    cudaGetSymbolAddress((void**)&gxs, g_GXs);
    cudaGetSymbolAddress((void**)&gxr, g_GXr);
    cudaGetSymbolAddress((void**)&hwB, g_Hw);
    cudaGetSymbolAddress((void**)&hsB, g_Hs);
    cudaGetSymbolAddress((void**)&hrB, g_Hr);
    cudaGetSymbolAddress((void**)&xs,  g_Xs);
    cudaGetSymbolAddress((void**)&xr,  g_Xr);
    cudaGetSymbolAddress((void**)&xb,  g_Xb);

    float* hw1 = hwB + (size_t)2 * NW * HD;
    float* hs1 = hsB + (size_t)2 * NS * HD;
    float* hr1 = hrB + (size_t)2 * NR * HD;

    // init barrier state + zero initial hidden states
    kinit_bar<<<1, 32>>>();
    kzero<<<2048, 256>>>(hwB, (size_t)2 * NW * HD);
    kzero<<<256,  256>>>(hsB, (size_t)2 * NS * HD);
    kzero<<<16,   256>>>(hrB, (size_t)2 * NR * HD);

    // project full vocabulary once per direction: PV = emb @ Wih^T + bih
    gemm_proj_mma<<<dim3((VOCAB + 127) / 128, G3 / 64, 2), 256, GEMM_SMEM_BYTES>>>(
        emb, VOCAB, wWih, wbih, pv);

    // word-level scan (T=32), persistent: 256 CTAs (2/SM)
    gru_scan<<<dim3(NW / 256, 16, 2), 256, SCAN_SMEM_BYTES>>>(
        hwB, hw1, wWhh, wbhh, nullptr, pv, tok, NW, TW, 0, NW / 256 * 16 * 2);
    sum_dirs<<<(NW * HD) / 256, 256>>>((TW & 1) ? hw1 : hwB, xs, NW);

    // sentence-level: project + persistent scan (T=16), 32 CTAs
    gemm_proj_mma<<<dim3((NW + 127) / 128, G3 / 64, 2), 256, GEMM_SMEM_BYTES>>>(
        xs, NW, sWih, sbih, gxs);
    gru_scan<<<dim3(1, 16, 2), 256, SCAN_SMEM_BYTES>>>(
        hsB, hs1, sWhh, sbhh, gxs, nullptr, nullptr, NS, TS, 1, 32);
    sum_dirs<<<(NS * HD) / 256, 256>>>((TS & 1) ? hs1 : hsB, xr, NS);

    // review-star head on review vectors -> out[8..135]
    fc_head<<<NS, 128>>>(xr, rfcW1, rfcb1, rfcW2, rfcb2, out + NR);

    // review-level (business) biGRU: project + persistent scan (T=16), 32 CTAs
    gemm_proj_mma<<<dim3(1, G3 / 64, 2), 256, GEMM_SMEM_BYTES>>>(xr, NS, rWih, rbih, gxr);
    gru_scan<<<dim3(1, 16, 2), 256, SCAN_SMEM_BYTES>>>(
        hrB, hr1, rWhh, rbhh, gxr, nullptr, nullptr, NR, TR, 2, 32);
    sum_dirs<<<(NR * HD) / 256, 256>>>((TR & 1) ? hr1 : hrB, xb, NR);

    // business head -> out[0..7]
    fc_head<<<NR, 128>>>(xb, pfcW1, pfcb1, pfcW2, pfcb2, out);

    (void)in_sizes; (void)n_in; (void)out_size;
}

// round 6
// speedup vs baseline: 2.6406x; 1.1635x over previous
#include <cuda_runtime.h>
#include <cstdint>

// ---------------- problem constants ----------------
#define HD   256      // hidden / embedding dim
#define G3   768      // 3*H gate dim
#define VOCAB 30000
#define NW   2048     // word-level sequences (B*R*S)
#define TW   32       // word-level timesteps (W)
#define NS   128      // sentence-level sequences (B*R)
#define TS   16       // sentence-level timesteps (S)
#define NR   8        // review-level sequences (B)
#define TR   16       // review-level timesteps (R)

#define SP   36       // smem row stride (mod 32 == 4 -> conflict-free frags)
#define WSP  260      // resident-W row stride (mod 32 == 4)

// scan smem: Wres[48*WSP] + Hsm[256*SP]  (unsigned words)
#define SCAN_SMEM_WORDS (48*WSP + 256*SP)
#define SCAN_SMEM_BYTES (SCAN_SMEM_WORDS * 4)
// gemm smem: double-buffered As[2][128][SP] + Bs[2][64][SP]
#define GEMM_SMEM_WORDS (2*128*SP + 2*64*SP)
#define GEMM_SMEM_BYTES (GEMM_SMEM_WORDS * 4)

// ---------------- scratch (static device globals; no runtime alloc) ----------------
__device__ float g_PV [(size_t)2*VOCAB*G3];        // projected vocab per dir
__device__ float g_GXs[(size_t)2*NS*TS*G3];        // sentence-level gx
__device__ float g_GXr[(size_t)2*NR*TR*G3];        // review-level gx
__device__ float g_Hw [2][(size_t)2*NW*HD];        // ping-pong hidden, word
__device__ float g_Hs [2][(size_t)2*NS*HD];        // sentence
__device__ float g_Hr [2][(size_t)2*NR*HD];        // review
__device__ float g_Xs [(size_t)NW*HD];             // sentence vectors (h_f+h_b)
__device__ float g_Xr [(size_t)NS*HD];             // review vectors
__device__ float g_Xb [(size_t)NR*HD];             // business vectors

// grid-barrier state (one per scan-direction)
__device__ unsigned g_cnt[8];
__device__ volatile unsigned g_phase[8];

// ---------------- helpers ----------------
__device__ __forceinline__ float fsigm(float x) {
    float e = __expf(-x);
    return __fdividef(1.f, 1.f + e);
}
__device__ __forceinline__ float ftanh(float x) {
    float ax = fabsf(x);
    float e = __expf(-2.f * ax);
    float r = __fdividef(1.f - e, 1.f + e);
    return copysignf(r, x);
}

__device__ __forceinline__ unsigned f2tf(float x) {
    unsigned u;
    asm("cvt.rna.tf32.f32 %0, %1;" : "=r"(u) : "f"(x));
    return u;
}

__device__ __forceinline__ void mma8(float* d,
                                     unsigned a0, unsigned a1, unsigned a2, unsigned a3,
                                     unsigned b0, unsigned b1) {
    asm volatile(
        "mma.sync.aligned.m16n8k8.row.col.f32.tf32.tf32.f32 "
        "{%0,%1,%2,%3},{%4,%5,%6,%7},{%8,%9},{%0,%1,%2,%3};"
        : "+f"(d[0]), "+f"(d[1]), "+f"(d[2]), "+f"(d[3])
        : "r"(a0), "r"(a1), "r"(a2), "r"(a3), "r"(b0), "r"(b1));
}

__device__ __forceinline__ void ldsm4(unsigned& r0, unsigned& r1, unsigned& r2, unsigned& r3,
                                      unsigned addr) {
    asm volatile("ldmatrix.sync.aligned.m8n8.x4.shared.b16 {%0,%1,%2,%3}, [%4];"
                 : "=r"(r0), "=r"(r1), "=r"(r2), "=r"(r3) : "r"(addr));
}
__device__ __forceinline__ void ldsm2(unsigned& r0, unsigned& r1, unsigned addr) {
    asm volatile("ldmatrix.sync.aligned.m8n8.x2.shared.b16 {%0,%1}, [%2];"
                 : "=r"(r0), "=r"(r1) : "r"(addr));
}

__global__ void kinit_bar() {
    if (threadIdx.x < 8) { g_cnt[threadIdx.x] = 0; g_phase[threadIdx.x] = 0; }
}

__global__ void kzero(float* p, size_t n) {
    size_t i = (size_t)blockIdx.x * blockDim.x + threadIdx.x;
    size_t stride = (size_t)gridDim.x * blockDim.x;
    for (; i < n; i += stride) p[i] = 0.f;
}

// software grid barrier: all nCTA blocks (of this barrier id) must be co-resident
__device__ __forceinline__ void gbar(int id, unsigned nCTA, unsigned target) {
    __syncthreads();
    if (threadIdx.x == 0) {
        __threadfence();
        unsigned old = atomicAdd(&g_cnt[id], 1u);
        if (old == nCTA - 1u) {
            g_cnt[id] = 0u;
            __threadfence();
            g_phase[id] = target;
        } else {
            while (g_phase[id] < target) __nanosleep(64);
        }
        __threadfence();
    }
    __syncthreads();
}

// ---------------- TF32 GEMM: C[d][M,768] = A[M,256] @ W[d][768,256]^T + bias[d] ----------------
// CTA 128(m) x 64(n), block 256, warps 4m x 2n, warp tile 32x32 (mt=2, nt=4)
// double-buffered smem, one sync per k-chunk, LDSM fragments. grid: (ceil(M/128), 12, 2)
__global__ __launch_bounds__(256, 2)
void gemm_proj_mma(const float* __restrict__ A, int M,
                   const float* __restrict__ W, const float* __restrict__ bias,
                   float* __restrict__ C)
{
    extern __shared__ unsigned gsm[];
    unsigned* As = gsm;                  // [2][128][SP]
    unsigned* Bs = gsm + 2 * 128 * SP;   // [2][64][SP]

    int d = blockIdx.z;
    const float* Wd = W    + (size_t)d * G3 * HD;
    const float* bd = bias + (size_t)d * G3;
    float*       Cd = C    + (size_t)d * M * G3;

    int m0 = blockIdx.x * 128;
    int n0 = blockIdx.y * 64;

    int tid = threadIdx.x, lane = tid & 31, wid = tid >> 5;
    int wm = wid & 3, wn = wid >> 2;
    int RB = wm * 32, CB = wn * 32;
    int g = lane >> 2, c = lane & 3;

    // ldmatrix lane roles
    int l7 = lane & 7, ts = lane >> 3;
    int a_row_off = l7 + (ts & 1) * 8;      // within 16-row tile
    int a_col_off = (ts >> 1) * 4;          // 0 or 4 words
    unsigned sAs = (unsigned)__cvta_generic_to_shared(As);
    unsigned sBs = (unsigned)__cvta_generic_to_shared(Bs);

    unsigned aAddr[2], bAddr[2];
#pragma unroll
    for (int mt = 0; mt < 2; ++mt)
        aAddr[mt] = sAs + (unsigned)(((RB + mt * 16 + a_row_off) * SP + a_col_off) * 4);
    // b x4 covers nt pair (2p, 2p+1): tile ts -> nt_local = ts>>1, colsel = (ts&1)*4
    int ntl = ts >> 1, bcol = (ts & 1) * 4;
#pragma unroll
    for (int p = 0; p < 2; ++p)
        bAddr[p] = sBs + (unsigned)(((CB + (2 * p + ntl) * 8 + l7) * SP + bcol) * 4);

    float acc[2][4][4];
#pragma unroll
    for (int i = 0; i < 2; ++i)
#pragma unroll
        for (int j = 0; j < 4; ++j)
#pragma unroll
            for (int k = 0; k < 4; ++k) acc[i][j][k] = 0.f;

    int lr = tid >> 3, lq = tid & 7;

    float4 pa[4], pw[2];
#pragma unroll
    for (int it = 0; it < 4; ++it) {
        int r = lr + it * 32;
        pa[it] = make_float4(0.f, 0.f, 0.f, 0.f);
        if (m0 + r < M) pa[it] = *(const float4*)(A + (size_t)(m0 + r) * HD + lq * 4);
    }
#pragma unroll
    for (int it = 0; it < 2; ++it) {
        int r = lr + it * 32;
        pw[it] = *(const float4*)(Wd + (size_t)(n0 + r) * HD + lq * 4);
    }
#pragma unroll
    for (int it = 0; it < 4; ++it) {
        int r = lr + it * 32;
        *(uint4*)(As + (size_t)r * SP + lq * 4) =
            make_uint4(f2tf(pa[it].x), f2tf(pa[it].y), f2tf(pa[it].z), f2tf(pa[it].w));
    }
#pragma unroll
    for (int it = 0; it < 2; ++it) {
        int r = lr + it * 32;
        *(uint4*)(Bs + (size_t)r * SP + lq * 4) =
            make_uint4(f2tf(pw[it].x), f2tf(pw[it].y), f2tf(pw[it].z), f2tf(pw[it].w));
    }
    __syncthreads();

    for (int k0i = 0; k0i < 8; ++k0i) {
        int cur = k0i & 1;
        if (k0i < 7) {
            int k0 = (k0i + 1) * 32;
#pragma unroll
            for (int it = 0; it < 4; ++it) {
                int r = lr + it * 32;
                pa[it] = make_float4(0.f, 0.f, 0.f, 0.f);
                if (m0 + r < M) pa[it] = *(const float4*)(A + (size_t)(m0 + r) * HD + k0 + lq * 4);
            }
#pragma unroll
            for (int it = 0; it < 2; ++it) {
                int r = lr + it * 32;
                pw[it] = *(const float4*)(Wd + (size_t)(n0 + r) * HD + k0 + lq * 4);
            }
        }

        unsigned aBuf = (unsigned)(cur * 128 * SP * 4);
        unsigned bBuf = (unsigned)(cur * 64 * SP * 4);
#pragma unroll
        for (int ks = 0; ks < 4; ++ks) {
            unsigned kbo = (unsigned)(ks * 32);  // bytes (8 words)
            unsigned a[2][4];
#pragma unroll
            for (int mt = 0; mt < 2; ++mt)
                ldsm4(a[mt][0], a[mt][1], a[mt][2], a[mt][3], aAddr[mt] + aBuf + kbo);
            unsigned b[4][2];
#pragma unroll
            for (int p = 0; p < 2; ++p)
                ldsm4(b[2*p][0], b[2*p][1], b[2*p+1][0], b[2*p+1][1], bAddr[p] + bBuf + kbo);
#pragma unroll
            for (int nt = 0; nt < 4; ++nt)
#pragma unroll
                for (int mt = 0; mt < 2; ++mt)
                    mma8(acc[mt][nt], a[mt][0], a[mt][1], a[mt][2], a[mt][3],
                         b[nt][0], b[nt][1]);
        }

        if (k0i < 7) {
            unsigned* An = As + (size_t)(cur ^ 1) * 128 * SP;
            unsigned* Bn = Bs + (size_t)(cur ^ 1) * 64 * SP;
#pragma unroll
            for (int it = 0; it < 4; ++it) {
                int r = lr + it * 32;
                *(uint4*)(An + (size_t)r * SP + lq * 4) =
                    make_uint4(f2tf(pa[it].x), f2tf(pa[it].y), f2tf(pa[it].z), f2tf(pa[it].w));
            }
#pragma unroll
            for (int it = 0; it < 2; ++it) {
                int r = lr + it * 32;
                *(uint4*)(Bn + (size_t)r * SP + lq * 4) =
                    make_uint4(f2tf(pw[it].x), f2tf(pw[it].y), f2tf(pw[it].z), f2tf(pw[it].w));
            }
        }
        __syncthreads();
    }

#pragma unroll
    for (int nt = 0; nt < 4; ++nt) {
        int col = n0 + CB + nt * 8 + 2 * c;
        float2 bb = *(const float2*)(bd + col);
#pragma unroll
        for (int mt = 0; mt < 2; ++mt) {
            int row0 = m0 + RB + mt * 16 + g;
            if (row0 < M) {
                float2 o = make_float2(acc[mt][nt][0] + bb.x, acc[mt][nt][1] + bb.y);
                *(float2*)(Cd + (size_t)row0 * G3 + col) = o;
            }
            int row1 = row0 + 8;
            if (row1 < M) {
                float2 o = make_float2(acc[mt][nt][2] + bb.x, acc[mt][nt][3] + bb.y);
                *(float2*)(Cd + (size_t)row1 * G3 + col) = o;
            }
        }
    }
}

// ---------------- persistent fused GRU scan (all T steps in one launch) ----------------
// CTA tile: 256 rows x 16 j-cols x 3 gates; W slice resident in smem; 2 CTAs/SM.
// grid: (ceil(N/256), 16, 2); per-direction grid barrier per step.
// warps 4m x 2n; warp tile 64 rows x 8 j x 3 gates (mt=4); LDSM fragments.
__global__ __launch_bounds__(256, 2)
void gru_scan(float* __restrict__ H0, float* __restrict__ H1,
              const float* __restrict__ Whh,   // [2][768][256]
              const float* __restrict__ bhh,   // [2][768]
              const float* __restrict__ GX,    // [2][N*T][768] or nullptr
              const float* __restrict__ PV,    // [2][VOCAB][768] or nullptr
              const int*   __restrict__ tok,   // tokens or nullptr
              int N, int T, int barId, unsigned nCTA)
{
    extern __shared__ unsigned smem[];
    unsigned* Wres = smem;                                     // [48][WSP] rows: gt*16+j
    unsigned (*Hsm)[SP] = (unsigned(*)[SP])(smem + 48 * WSP);  // [256][SP]

    int d  = blockIdx.z;
    int n0 = blockIdx.x * 256;
    int j0 = blockIdx.y * 16;
    int bid = barId + d;

    const float* Wd = Whh + (size_t)d * G3 * HD;

    int tid = threadIdx.x, lane = tid & 31, wid = tid >> 5;
    int wm = wid & 3, wn = wid >> 2;
    int RB = wm * 64, CB = wn * 8;
    int g = lane >> 2, c = lane & 3;

    // ---- load resident W slice: 48 rows (gt*16 + j), 256 cols ----
    for (int idx = tid; idx < 48 * 64; idx += 256) {
        int row = idx >> 6;
        int c4  = idx & 63;
        int gt = row >> 4, j = row & 15;
        float4 v = *(const float4*)(Wd + (size_t)(gt * 256 + j0 + j) * HD + c4 * 4);
        *(uint4*)(Wres + (size_t)row * WSP + c4 * 4) =
            make_uint4(f2tf(v.x), f2tf(v.y), f2tf(v.z), f2tf(v.w));
    }
    __syncthreads();

    // ldmatrix lane roles
    int l7 = lane & 7, ts = lane >> 3;
    int a_row_off = l7 + (ts & 1) * 8;
    int a_col_off = (ts >> 1) * 4;
    unsigned sH = (unsigned)__cvta_generic_to_shared(Hsm);
    unsigned sW = (unsigned)__cvta_generic_to_shared(Wres);

    unsigned aAddr[4];
#pragma unroll
    for (int mt = 0; mt < 4; ++mt)
        aAddr[mt] = sH + (unsigned)(((RB + mt * 16 + a_row_off) * SP + a_col_off) * 4);
    // b x4: tiles = gate(ts>>1 in {0,1}), col (ts&1)*4
    unsigned bAddr01 = sW + (unsigned)((((ts >> 1) * 16 + CB + l7) * WSP + (ts & 1) * 4) * 4);
    // b x2 (gate 2): lanes 0-15: col ((lane>>3)&1)*4
    unsigned bAddr2  = sW + (unsigned)(((32 + CB + l7) * WSP + ((ts & 1) * 4)) * 4);

    bool is64 = false;
    if (tok) is64 = (tok[1] == 0) & (tok[3] == 0) & (tok[5] == 0) & (tok[7] == 0);

    // gate biases: invariant across steps and row-instances
    int cc = j0 + CB + 2 * c;
    float2 br2 = *(const float2*)(bhh + (size_t)d * G3 + cc);
    float2 bz2 = *(const float2*)(bhh + (size_t)d * G3 + 256 + cc);
    float2 bn2 = *(const float2*)(bhh + (size_t)d * G3 + 512 + cc);

    int lr = tid >> 3, lq = tid & 7;

    for (int t = 0; t < T; ++t) {
        const float* Hin  = (t & 1) ? H1 : H0;
        float*       Hout = (t & 1) ? H0 : H1;
        int teff = d ? (T - 1 - t) : t;

        float acc[3][4][4];
#pragma unroll
        for (int i = 0; i < 3; ++i)
#pragma unroll
            for (int j = 0; j < 4; ++j)
#pragma unroll
                for (int k = 0; k < 4; ++k) acc[i][j][k] = 0.f;

        // prefetch H chunk 0
        float4 ph[8];
#pragma unroll
        for (int it = 0; it < 8; ++it) {
            int r = lr + it * 32;
            ph[it] = make_float4(0.f, 0.f, 0.f, 0.f);
            if (n0 + r < N)
                ph[it] = *(const float4*)(Hin + (size_t)(d * N + n0 + r) * HD + lq * 4);
        }

        for (int k0i = 0; k0i < 8; ++k0i) {
#pragma unroll
            for (int it = 0; it < 8; ++it) {
                int r = lr + it * 32;
                *(uint4*)(&Hsm[r][lq * 4]) =
                    make_uint4(f2tf(ph[it].x), f2tf(ph[it].y), f2tf(ph[it].z), f2tf(ph[it].w));
            }
            __syncthreads();

            if (k0i < 7) {
                int k0 = (k0i + 1) * 32;
#pragma unroll
                for (int it = 0; it < 8; ++it) {
                    int r = lr + it * 32;
                    ph[it] = make_float4(0.f, 0.f, 0.f, 0.f);
                    if (n0 + r < N)
                        ph[it] = *(const float4*)(Hin + (size_t)(d * N + n0 + r) * HD + k0 + lq * 4);
                }
            }

            unsigned kwo = (unsigned)(k0i * 128);  // kbase bytes into Wres rows
#pragma unroll
            for (int ks = 0; ks < 4; ++ks) {
                unsigned kbo = (unsigned)(ks * 32);
                unsigned a[4][4];
#pragma unroll
                for (int mt = 0; mt < 4; ++mt)
                    ldsm4(a[mt][0], a[mt][1], a[mt][2], a[mt][3], aAddr[mt] + kbo);
                unsigned b00, b01, b10, b11, b20, b21;
                ldsm4(b00, b01, b10, b11, bAddr01 + kwo + kbo);
                ldsm2(b20, b21, bAddr2 + kwo + kbo);
#pragma unroll
                for (int mt = 0; mt < 4; ++mt) {
                    mma8(acc[0][mt], a[mt][0], a[mt][1], a[mt][2], a[mt][3], b00, b01);
                    mma8(acc[1][mt], a[mt][0], a[mt][1], a[mt][2], a[mt][3], b10, b11);
                    mma8(acc[2][mt], a[mt][0], a[mt][1], a[mt][2], a[mt][3], b20, b21);
                }
            }
            __syncthreads();
        }

        // ---- gate math epilogue: 8 row-instances, processed in 2 phases of 4 ----
#pragma unroll
        for (int phx = 0; phx < 2; ++phx) {
            float2 GR[4], GZ[4], GN[4], HH[4];
            float* orow_[4];
            bool val[4];
#pragma unroll
            for (int i = 0; i < 4; ++i) {
                int idx = phx * 4 + i;
                int mt = idx >> 1, half = idx & 1;
                int r = n0 + RB + mt * 16 + g + half * 8;
                val[i] = (r < N);
                GR[i] = GZ[i] = GN[i] = HH[i] = make_float2(0.f, 0.f);
                orow_[i] = Hout + (size_t)(d * N + r) * HD;
                if (val[i]) {
                    const float* gxrow;
                    if (tok) {
                        int ti = r * T + teff;
                        int tv = is64 ? tok[2 * (size_t)ti] : tok[ti];
                        gxrow = PV + ((size_t)d * VOCAB + tv) * G3;
                    } else {
                        gxrow = GX + ((size_t)d * N * T + (size_t)r * T + teff) * G3;
                    }
                    GR[i] = *(const float2*)(gxrow + cc);
                    GZ[i] = *(const float2*)(gxrow + 256 + cc);
                    GN[i] = *(const float2*)(gxrow + 512 + cc);
                    HH[i] = *(const float2*)(Hin + (size_t)(d * N + r) * HD + cc);
                }
            }
#pragma unroll
            for (int i = 0; i < 4; ++i) {
                if (!val[i]) continue;
                int idx = phx * 4 + i;
                int mt = idx >> 1, half = idx & 1;
                float aR0 = acc[0][mt][half * 2 + 0], aR1 = acc[0][mt][half * 2 + 1];
                float aZ0 = acc[1][mt][half * 2 + 0], aZ1 = acc[1][mt][half * 2 + 1];
                float aN0 = acc[2][mt][half * 2 + 0], aN1 = acc[2][mt][half * 2 + 1];

                float r0 = fsigm(GR[i].x + aR0 + br2.x);
                float r1 = fsigm(GR[i].y + aR1 + br2.y);
                float z0 = fsigm(GZ[i].x + aZ0 + bz2.x);
                float z1 = fsigm(GZ[i].y + aZ1 + bz2.y);
                float n0v = ftanh(GN[i].x + r0 * (aN0 + bn2.x));
                float n1v = ftanh(GN[i].y + r1 * (aN1 + bn2.y));

                float2 o;
                o.x = (1.f - z0) * n0v + z0 * HH[i].x;
                o.y = (1.f - z1) * n1v + z1 * HH[i].y;
                *(float2*)(orow_[i] + cc) = o;
            }
        }

        gbar(bid, nCTA, (unsigned)(t + 1));
    }
}

// ---------------- sum forward+backward final hidden ----------------
__global__ void sum_dirs(const float* __restrict__ Hf, float* __restrict__ out, int N)
{
    int i = blockIdx.x * 256 + threadIdx.x;
    if (i < N * HD) out[i] = Hf[i] + Hf[(size_t)N * HD + i];
}

// ---------------- FC head: Linear(256->128) -> SELU -> Linear(128->1) ----------------
__global__ void fc_head(const float* __restrict__ X,
                        const float* __restrict__ W1, const float* __restrict__ b1,
                        const float* __restrict__ W2, const float* __restrict__ b2,
                        float* __restrict__ out)
{
    int row = blockIdx.x;
    int h = threadIdx.x;  // 128 threads
    const float* x = X + (size_t)row * HD;
    const float* w = W1 + (size_t)h * HD;
    float s = 0.f;
#pragma unroll 8
    for (int k = 0; k < HD; k += 4) {
        float4 xv = *(const float4*)(x + k);
        float4 wv = *(const float4*)(w + k);
        s += xv.x * wv.x + xv.y * wv.y + xv.z * wv.z + xv.w * wv.w;
    }
    s += b1[h];
    const float SC = 1.0507009873554805f, AL = 1.6732632423543772f;
    float selu = SC * (s > 0.f ? s : AL * expm1f(s));
    float v = selu * W2[h];
    __shared__ float red[128];
    red[h] = v; __syncthreads();
    for (int st = 64; st > 0; st >>= 1) {
        if (h < st) red[h] += red[h + st];
        __syncthreads();
    }
    if (h == 0) out[row] = red[0] + b2[0];
}

// ---------------- launch ----------------
extern "C" void kernel_launch(void* const* d_in, const int* in_sizes, int n_in,
                              void* d_out, int out_size)
{
    const int*   tok   = (const int*)  d_in[0];
    const float* emb   = (const float*)d_in[1];
    const float* wWih  = (const float*)d_in[2];
    const float* wWhh  = (const float*)d_in[3];
    const float* wbih  = (const float*)d_in[4];
    const float* wbhh  = (const float*)d_in[5];
    const float* sWih  = (const float*)d_in[6];
    const float* sWhh  = (const float*)d_in[7];
    const float* sbih  = (const float*)d_in[8];
    const float* sbhh  = (const float*)d_in[9];
    const float* rWih  = (const float*)d_in[10];
    const float* rWhh  = (const float*)d_in[11];
    const float* rbih  = (const float*)d_in[12];
    const float* rbhh  = (const float*)d_in[13];
    const float* rfcW1 = (const float*)d_in[14];
    const float* rfcb1 = (const float*)d_in[15];
    const float* rfcW2 = (const float*)d_in[16];
    const float* rfcb2 = (const float*)d_in[17];
    const float* pfcW1 = (const float*)d_in[18];
    const float* pfcb1 = (const float*)d_in[19];
    const float* pfcW2 = (const float*)d_in[20];
    const float* pfcb2 = (const float*)d_in[21];
    float* out = (float*)d_out;

    static bool attr_set = false;
    if (!attr_set) {
        cudaFuncSetAttribute(gru_scan, cudaFuncAttributeMaxDynamicSharedMemorySize,
                             SCAN_SMEM_BYTES);
        cudaFuncSetAttribute(gemm_proj_mma, cudaFuncAttributeMaxDynamicSharedMemorySize,
                             GEMM_SMEM_BYTES);
        attr_set = true;
    }

    float *pv, *gxs, *gxr, *hwB, *hsB, *hrB, *xs, *xr, *xb;
    cudaGetSymbolAddress((void**)&pv,  g_PV);
    cudaGetSymbolAddress((void**)&gxs, g_GXs);
    cudaGetSymbolAddress((void**)&gxr, g_GXr);
    cudaGetSymbolAddress((void**)&hwB, g_Hw);
    cudaGetSymbolAddress((void**)&hsB, g_Hs);
    cudaGetSymbolAddress((void**)&hrB, g_Hr);
    cudaGetSymbolAddress((void**)&xs,  g_Xs);
    cudaGetSymbolAddress((void**)&xr,  g_Xr);
    cudaGetSymbolAddress((void**)&xb,  g_Xb);

    float* hw1 = hwB + (size_t)2 * NW * HD;
    float* hs1 = hsB + (size_t)2 * NS * HD;
    float* hr1 = hrB + (size_t)2 * NR * HD;

    // init barrier state + zero initial hidden states
    kinit_bar<<<1, 32>>>();
    kzero<<<2048, 256>>>(hwB, (size_t)2 * NW * HD);
    kzero<<<256,  256>>>(hsB, (size_t)2 * NS * HD);
    kzero<<<16,   256>>>(hrB, (size_t)2 * NR * HD);

    // project full vocabulary once per direction: PV = emb @ Wih^T + bih
    gemm_proj_mma<<<dim3((VOCAB + 127) / 128, G3 / 64, 2), 256, GEMM_SMEM_BYTES>>>(
        emb, VOCAB, wWih, wbih, pv);

    // word-level scan (T=32), persistent: 256 CTAs (128 per dir-barrier)
    gru_scan<<<dim3(NW / 256, 16, 2), 256, SCAN_SMEM_BYTES>>>(
        hwB, hw1, wWhh, wbhh, nullptr, pv, tok, NW, TW, 0, NW / 256 * 16);
    sum_dirs<<<(NW * HD) / 256, 256>>>((TW & 1) ? hw1 : hwB, xs, NW);

    // sentence-level: project + persistent scan (T=16), 16 CTAs per dir
    gemm_proj_mma<<<dim3((NW + 127) / 128, G3 / 64, 2), 256, GEMM_SMEM_BYTES>>>(
        xs, NW, sWih, sbih, gxs);
    gru_scan<<<dim3(1, 16, 2), 256, SCAN_SMEM_BYTES>>>(
        hsB, hs1, sWhh, sbhh, gxs, nullptr, nullptr, NS, TS, 2, 16);
    sum_dirs<<<(NS * HD) / 256, 256>>>((TS & 1) ? hs1 : hsB, xr, NS);

    // review-star head on review vectors -> out[8..135]
    fc_head<<<NS, 128>>>(xr, rfcW1, rfcb1, rfcW2, rfcb2, out + NR);

    // review-level (business) biGRU: project + persistent scan (T=16), 16 CTAs per dir
    gemm_proj_mma<<<dim3(1, G3 / 64, 2), 256, GEMM_SMEM_BYTES>>>(xr, NS, rWih, rbih, gxr);
    gru_scan<<<dim3(1, 16, 2), 256, SCAN_SMEM_BYTES>>>(
        hrB, hr1, rWhh, rbhh, gxr, nullptr, nullptr, NR, TR, 4, 16);
    sum_dirs<<<(NR * HD) / 256, 256>>>((TR & 1) ? hr1 : hrB, xb, NR);

    // business head -> out[0..7]
    fc_head<<<NR, 128>>>(xb, pfcW1, pfcb1, pfcW2, pfcb2, out);

    (void)in_sizes; (void)n_in; (void)out_size;
}